// round 1
// baseline (speedup 1.0000x reference)
#include <cuda_runtime.h>

#define B_ 4
#define N_ 2048
#define C_ 768
#define H_ 12
#define R_ 32
#define M_ (B_ * N_)          // 8192 rows
#define HR_ (H_ * R_)         // 384

// Scratch (device globals; no allocations allowed)
__device__ float g_q[B_ * H_ * N_ * R_];
__device__ float g_k[B_ * H_ * N_ * R_];
__device__ float g_v[B_ * H_ * N_ * R_];
__device__ float g_o[B_ * N_ * HR_];

// ---------------------------------------------------------------------------
// Tiled SGEMM: C = A[M,K] @ W[K,Nc]
// mode 0: C row-major [M, Nc]
// mode 1: scatter into [B, H, N_, R_] layout (for q/k/v)
// BM=BN=64, BK=16, 256 threads, 4x4 per-thread microtile.
// ---------------------------------------------------------------------------
__global__ __launch_bounds__(256) void sgemm_kernel(
    const float* __restrict__ A, const float* __restrict__ W,
    float* __restrict__ Cout, int M, int K, int Nc, int mode)
{
    __shared__ float As[16][64];   // [k][m]
    __shared__ float Ws[16][64];   // [k][n]

    const int tid = threadIdx.x;
    const int tx = tid & 15;       // 0..15 -> col group
    const int ty = tid >> 4;       // 0..15 -> row group
    const int rowBase = blockIdx.y * 64;
    const int colBase = blockIdx.x * 64;

    // load indexing
    const int ar = tid >> 2;              // 0..63 row within A tile
    const int ak = (tid & 3) * 4;         // k offset (float4)
    const int wk = tid >> 4;              // 0..15 k row within W tile
    const int wn = (tid & 15) * 4;        // n offset (float4)

    const float* Aptr = A + (size_t)(rowBase + ar) * K + ak;
    const float* Wptr = W + (size_t)wk * Nc + colBase + wn;

    float acc[4][4] = {};

    for (int k0 = 0; k0 < K; k0 += 16) {
        float4 av = *(const float4*)(Aptr + k0);
        float4 wv = *(const float4*)(Wptr + (size_t)k0 * Nc);

        __syncthreads();
        As[ak + 0][ar] = av.x;
        As[ak + 1][ar] = av.y;
        As[ak + 2][ar] = av.z;
        As[ak + 3][ar] = av.w;
        *(float4*)&Ws[wk][wn] = wv;
        __syncthreads();

#pragma unroll
        for (int kk = 0; kk < 16; kk++) {
            float4 a = *(const float4*)&As[kk][ty * 4];
            float4 w = *(const float4*)&Ws[kk][tx * 4];
            acc[0][0] += a.x * w.x; acc[0][1] += a.x * w.y; acc[0][2] += a.x * w.z; acc[0][3] += a.x * w.w;
            acc[1][0] += a.y * w.x; acc[1][1] += a.y * w.y; acc[1][2] += a.y * w.z; acc[1][3] += a.y * w.w;
            acc[2][0] += a.z * w.x; acc[2][1] += a.z * w.y; acc[2][2] += a.z * w.z; acc[2][3] += a.z * w.w;
            acc[3][0] += a.w * w.x; acc[3][1] += a.w * w.y; acc[3][2] += a.w * w.z; acc[3][3] += a.w * w.w;
        }
    }

#pragma unroll
    for (int i = 0; i < 4; i++) {
#pragma unroll
        for (int j = 0; j < 4; j++) {
            int row = rowBase + ty * 4 + i;
            int col = colBase + tx * 4 + j;
            if (mode == 0) {
                Cout[(size_t)row * Nc + col] = acc[i][j];
            } else {
                int b = row >> 11;        // row / 2048
                int n = row & (N_ - 1);
                int h = col >> 5;         // col / 32
                int rr = col & (R_ - 1);
                Cout[((((size_t)b * H_ + h) * N_) + n) * R_ + rr] = acc[i][j];
            }
        }
    }
}

// ---------------------------------------------------------------------------
// Flash-style attention. One thread owns one query row (r=32 in registers).
// K/V tiles of 32 keys in shared memory. Online softmax (exact).
// grid: (N_/64, B_*H_), block: 64 threads.
// ---------------------------------------------------------------------------
__global__ __launch_bounds__(64) void attn_kernel(
    const float* __restrict__ q, const float* __restrict__ k,
    const float* __restrict__ v, float* __restrict__ o)
{
    __shared__ float Ks[32][32];
    __shared__ float Vs[32][32];

    const int t = threadIdx.x;
    const int bh = blockIdx.y;
    const int qi = blockIdx.x * 64 + t;

    const float scale = 0.125f;   // HEAD_DIM^-0.5 = 64^-0.5

    // load q row, pre-scaled
    float qr[R_];
    {
        const float4* qp = (const float4*)(q + ((size_t)bh * N_ + qi) * R_);
#pragma unroll
        for (int d4 = 0; d4 < 8; d4++) {
            float4 f = qp[d4];
            qr[d4 * 4 + 0] = f.x * scale;
            qr[d4 * 4 + 1] = f.y * scale;
            qr[d4 * 4 + 2] = f.z * scale;
            qr[d4 * 4 + 3] = f.w * scale;
        }
    }

    float m = -1e30f, l = 0.0f;
    float oa[R_] = {};

    const float4* kbase = (const float4*)(k + (size_t)bh * N_ * R_);
    const float4* vbase = (const float4*)(v + (size_t)bh * N_ * R_);

    for (int kt = 0; kt < N_ / 32; kt++) {
        __syncthreads();
        int off = kt * 256;  // 32 keys * 32 floats / 4 = 256 float4
#pragma unroll
        for (int i = 0; i < 4; i++) {
            ((float4*)Ks)[t + i * 64] = kbase[off + t + i * 64];
            ((float4*)Vs)[t + i * 64] = vbase[off + t + i * 64];
        }
        __syncthreads();

        float s[32];
#pragma unroll
        for (int j = 0; j < 32; j++) {
            float accd = 0.0f;
#pragma unroll
            for (int d4 = 0; d4 < 8; d4++) {
                float4 kf = *(const float4*)&Ks[j][d4 * 4];
                accd += qr[d4 * 4 + 0] * kf.x;
                accd += qr[d4 * 4 + 1] * kf.y;
                accd += qr[d4 * 4 + 2] * kf.z;
                accd += qr[d4 * 4 + 3] * kf.w;
            }
            s[j] = accd;
        }

        float mt = m;
#pragma unroll
        for (int j = 0; j < 32; j++) mt = fmaxf(mt, s[j]);

        float alpha = __expf(m - mt);
        m = mt;
        l *= alpha;
#pragma unroll
        for (int d = 0; d < R_; d++) oa[d] *= alpha;

#pragma unroll
        for (int j = 0; j < 32; j++) {
            float p = __expf(s[j] - m);
            l += p;
#pragma unroll
            for (int d4 = 0; d4 < 8; d4++) {
                float4 vf = *(const float4*)&Vs[j][d4 * 4];
                oa[d4 * 4 + 0] += p * vf.x;
                oa[d4 * 4 + 1] += p * vf.y;
                oa[d4 * 4 + 2] += p * vf.z;
                oa[d4 * 4 + 3] += p * vf.w;
            }
        }
    }

    const float inv = 1.0f / l;
    const int b = bh / H_;
    const int h = bh % H_;
    float4* op = (float4*)(o + (((size_t)b * N_ + qi) * H_ + h) * R_);
#pragma unroll
    for (int d4 = 0; d4 < 8; d4++) {
        float4 f;
        f.x = oa[d4 * 4 + 0] * inv;
        f.y = oa[d4 * 4 + 1] * inv;
        f.z = oa[d4 * 4 + 2] * inv;
        f.w = oa[d4 * 4 + 3] * inv;
        op[d4] = f;
    }
}

// ---------------------------------------------------------------------------
extern "C" void kernel_launch(void* const* d_in, const int* in_sizes, int n_in,
                              void* d_out, int out_size)
{
    const float* x  = (const float*)d_in[0];
    const float* Wq = (const float*)d_in[1];
    const float* Wk = (const float*)d_in[2];
    const float* Wv = (const float*)d_in[3];
    const float* Wp = (const float*)d_in[4];
    float* out = (float*)d_out;

    float *gq, *gk, *gv, *go;
    cudaGetSymbolAddress((void**)&gq, g_q);
    cudaGetSymbolAddress((void**)&gk, g_k);
    cudaGetSymbolAddress((void**)&gv, g_v);
    cudaGetSymbolAddress((void**)&go, g_o);

    // QKV projections: [8192,768] @ [768,384] -> [B,H,N,32]
    dim3 gProj(HR_ / 64, M_ / 64);
    sgemm_kernel<<<gProj, 256>>>(x, Wq, gq, M_, C_, HR_, 1);
    sgemm_kernel<<<gProj, 256>>>(x, Wk, gk, M_, C_, HR_, 1);
    sgemm_kernel<<<gProj, 256>>>(x, Wv, gv, M_, C_, HR_, 1);

    // attention
    dim3 gAttn(N_ / 64, B_ * H_);
    attn_kernel<<<gAttn, 64>>>(gq, gk, gv, go);

    // output projection: [8192,384] @ [384,768] -> d_out
    dim3 gOut(C_ / 64, M_ / 64);
    sgemm_kernel<<<gOut, 256>>>(go, Wp, out, M_, HR_, C_, 0);
}

// round 2
// speedup vs baseline: 1.1141x; 1.1141x over previous
#include <cuda_runtime.h>

#define B_ 4
#define N_ 2048
#define C_ 768
#define H_ 12
#define R_ 32
#define M_ (B_ * N_)          // 8192 rows
#define HR_ (H_ * R_)         // 384

// Scratch (device globals; no allocations allowed)
__device__ float g_q[B_ * H_ * N_ * R_];
__device__ float g_k[B_ * H_ * N_ * R_];
__device__ float g_v[B_ * H_ * N_ * R_];
__device__ float g_o[B_ * N_ * HR_];

// ---------------------------------------------------------------------------
// Tiled SGEMM: C = A[M,K] @ W[K,Nc]
// mode 0: C row-major [M, Nc]
// mode 1: scatter into [B, H, N_, R_] layout (for q/k/v)
// BM=128, BN=64, BK=16, 256 threads, 8x4 per-thread microtile.
// ---------------------------------------------------------------------------
__global__ __launch_bounds__(256) void sgemm_kernel(
    const float* __restrict__ A, const float* __restrict__ W,
    float* __restrict__ Cout, int M, int K, int Nc, int mode)
{
    __shared__ float As[16][128];  // [k][m]
    __shared__ float Ws[16][64];   // [k][n]

    const int tid = threadIdx.x;
    const int tx = tid & 15;       // 0..15 -> col group (4 cols)
    const int ty = tid >> 4;       // 0..15 -> row group (8 rows)
    const int rowBase = blockIdx.y * 128;
    const int colBase = blockIdx.x * 64;

    // load indexing
    const int ar = tid >> 1;              // 0..127 row within A tile
    const int ak = (tid & 1) * 8;         // k offset (two float4)
    const int wk = tid >> 4;              // 0..15 k row within W tile
    const int wn = (tid & 15) * 4;        // n offset (float4)

    const float* Aptr = A + (size_t)(rowBase + ar) * K + ak;
    const float* Wptr = W + (size_t)wk * Nc + colBase + wn;

    float acc[8][4] = {};

    for (int k0 = 0; k0 < K; k0 += 16) {
        float4 av0 = *(const float4*)(Aptr + k0);
        float4 av1 = *(const float4*)(Aptr + k0 + 4);
        float4 wv  = *(const float4*)(Wptr + (size_t)k0 * Nc);

        __syncthreads();
        As[ak + 0][ar] = av0.x;
        As[ak + 1][ar] = av0.y;
        As[ak + 2][ar] = av0.z;
        As[ak + 3][ar] = av0.w;
        As[ak + 4][ar] = av1.x;
        As[ak + 5][ar] = av1.y;
        As[ak + 6][ar] = av1.z;
        As[ak + 7][ar] = av1.w;
        *(float4*)&Ws[wk][wn] = wv;
        __syncthreads();

#pragma unroll
        for (int kk = 0; kk < 16; kk++) {
            float4 a0 = *(const float4*)&As[kk][ty * 8];
            float4 a1 = *(const float4*)&As[kk][ty * 8 + 4];
            float4 w  = *(const float4*)&Ws[kk][tx * 4];
            acc[0][0] += a0.x * w.x; acc[0][1] += a0.x * w.y; acc[0][2] += a0.x * w.z; acc[0][3] += a0.x * w.w;
            acc[1][0] += a0.y * w.x; acc[1][1] += a0.y * w.y; acc[1][2] += a0.y * w.z; acc[1][3] += a0.y * w.w;
            acc[2][0] += a0.z * w.x; acc[2][1] += a0.z * w.y; acc[2][2] += a0.z * w.z; acc[2][3] += a0.z * w.w;
            acc[3][0] += a0.w * w.x; acc[3][1] += a0.w * w.y; acc[3][2] += a0.w * w.z; acc[3][3] += a0.w * w.w;
            acc[4][0] += a1.x * w.x; acc[4][1] += a1.x * w.y; acc[4][2] += a1.x * w.z; acc[4][3] += a1.x * w.w;
            acc[5][0] += a1.y * w.x; acc[5][1] += a1.y * w.y; acc[5][2] += a1.y * w.z; acc[5][3] += a1.y * w.w;
            acc[6][0] += a1.z * w.x; acc[6][1] += a1.z * w.y; acc[6][2] += a1.z * w.z; acc[6][3] += a1.z * w.w;
            acc[7][0] += a1.w * w.x; acc[7][1] += a1.w * w.y; acc[7][2] += a1.w * w.z; acc[7][3] += a1.w * w.w;
        }
    }

#pragma unroll
    for (int i = 0; i < 8; i++) {
#pragma unroll
        for (int j = 0; j < 4; j++) {
            int row = rowBase + ty * 8 + i;
            int col = colBase + tx * 4 + j;
            if (mode == 0) {
                Cout[(size_t)row * Nc + col] = acc[i][j];
            } else {
                int b = row >> 11;        // row / 2048
                int n = row & (N_ - 1);
                int h = col >> 5;         // col / 32
                int rr = col & (R_ - 1);
                Cout[((((size_t)b * H_ + h) * N_) + n) * R_ + rr] = acc[i][j];
            }
        }
    }
}

// ---------------------------------------------------------------------------
// Flash-style attention. One thread owns TWO query rows (amortizes broadcast
// K/V shared loads: per key, 16 LDS.128 serve 128 FFMAs).
// K/V tiles of 16 keys, double-buffered smem, 1 sync per tile.
// grid: (N_/256, B_*H_), block: 128 threads.
// ---------------------------------------------------------------------------
__global__ __launch_bounds__(128) void attn_kernel(
    const float* __restrict__ q, const float* __restrict__ k,
    const float* __restrict__ v, float* __restrict__ o)
{
    __shared__ float Ks[2][16][32];
    __shared__ float Vs[2][16][32];

    const int t = threadIdx.x;
    const int bh = blockIdx.y;
    const int qi0 = blockIdx.x * 256 + t;
    const int qi1 = qi0 + 128;

    const float scale = 0.125f;   // HEAD_DIM^-0.5 = 64^-0.5

    // load both q rows, pre-scaled
    float qr0[R_], qr1[R_];
    {
        const float4* qp0 = (const float4*)(q + ((size_t)bh * N_ + qi0) * R_);
        const float4* qp1 = (const float4*)(q + ((size_t)bh * N_ + qi1) * R_);
#pragma unroll
        for (int d4 = 0; d4 < 8; d4++) {
            float4 f0 = qp0[d4];
            float4 f1 = qp1[d4];
            qr0[d4 * 4 + 0] = f0.x * scale; qr0[d4 * 4 + 1] = f0.y * scale;
            qr0[d4 * 4 + 2] = f0.z * scale; qr0[d4 * 4 + 3] = f0.w * scale;
            qr1[d4 * 4 + 0] = f1.x * scale; qr1[d4 * 4 + 1] = f1.y * scale;
            qr1[d4 * 4 + 2] = f1.z * scale; qr1[d4 * 4 + 3] = f1.w * scale;
        }
    }

    float m0 = -1e30f, m1 = -1e30f, l0 = 0.0f, l1 = 0.0f;
    float oa0[R_] = {}, oa1[R_] = {};

    const float4* kbase = (const float4*)(k + (size_t)bh * N_ * R_);
    const float4* vbase = (const float4*)(v + (size_t)bh * N_ * R_);

    // preload tile 0 (16 keys * 32 floats = 128 float4; one per thread)
    ((float4*)Ks[0])[t] = kbase[t];
    ((float4*)Vs[0])[t] = vbase[t];
    __syncthreads();

    int p = 0;
    const int NT = N_ / 16;   // 128 tiles
    for (int kt = 0; kt < NT; kt++) {
        // prefetch next tile into registers (overlaps with compute below)
        int nxt = (kt + 1 < NT) ? kt + 1 : kt;
        float4 kn = kbase[nxt * 128 + t];
        float4 vn = vbase[nxt * 128 + t];

        // scores for both rows over 16 keys
        float s0[16], s1[16];
#pragma unroll
        for (int j = 0; j < 16; j++) {
            float a0 = 0.0f, a1 = 0.0f;
#pragma unroll
            for (int d4 = 0; d4 < 8; d4++) {
                float4 kf = *(const float4*)&Ks[p][j][d4 * 4];
                a0 += qr0[d4 * 4 + 0] * kf.x; a0 += qr0[d4 * 4 + 1] * kf.y;
                a0 += qr0[d4 * 4 + 2] * kf.z; a0 += qr0[d4 * 4 + 3] * kf.w;
                a1 += qr1[d4 * 4 + 0] * kf.x; a1 += qr1[d4 * 4 + 1] * kf.y;
                a1 += qr1[d4 * 4 + 2] * kf.z; a1 += qr1[d4 * 4 + 3] * kf.w;
            }
            s0[j] = a0;
            s1[j] = a1;
        }

        float mt0 = m0, mt1 = m1;
#pragma unroll
        for (int j = 0; j < 16; j++) { mt0 = fmaxf(mt0, s0[j]); mt1 = fmaxf(mt1, s1[j]); }

        float al0 = __expf(m0 - mt0);
        float al1 = __expf(m1 - mt1);
        m0 = mt0; m1 = mt1;
        l0 *= al0; l1 *= al1;
#pragma unroll
        for (int d = 0; d < R_; d++) { oa0[d] *= al0; oa1[d] *= al1; }

#pragma unroll
        for (int j = 0; j < 16; j++) {
            float p0 = __expf(s0[j] - m0);
            float p1 = __expf(s1[j] - m1);
            l0 += p0; l1 += p1;
#pragma unroll
            for (int d4 = 0; d4 < 8; d4++) {
                float4 vf = *(const float4*)&Vs[p][j][d4 * 4];
                oa0[d4 * 4 + 0] += p0 * vf.x; oa0[d4 * 4 + 1] += p0 * vf.y;
                oa0[d4 * 4 + 2] += p0 * vf.z; oa0[d4 * 4 + 3] += p0 * vf.w;
                oa1[d4 * 4 + 0] += p1 * vf.x; oa1[d4 * 4 + 1] += p1 * vf.y;
                oa1[d4 * 4 + 2] += p1 * vf.z; oa1[d4 * 4 + 3] += p1 * vf.w;
            }
        }

        // store prefetched tile into the other buffer; single sync per iter
        ((float4*)Ks[p ^ 1])[t] = kn;
        ((float4*)Vs[p ^ 1])[t] = vn;
        __syncthreads();
        p ^= 1;
    }

    const float inv0 = 1.0f / l0;
    const float inv1 = 1.0f / l1;
    const int b = bh / H_;
    const int h = bh % H_;
    float4* op0 = (float4*)(o + (((size_t)b * N_ + qi0) * H_ + h) * R_);
    float4* op1 = (float4*)(o + (((size_t)b * N_ + qi1) * H_ + h) * R_);
#pragma unroll
    for (int d4 = 0; d4 < 8; d4++) {
        float4 f0, f1;
        f0.x = oa0[d4 * 4 + 0] * inv0; f0.y = oa0[d4 * 4 + 1] * inv0;
        f0.z = oa0[d4 * 4 + 2] * inv0; f0.w = oa0[d4 * 4 + 3] * inv0;
        f1.x = oa1[d4 * 4 + 0] * inv1; f1.y = oa1[d4 * 4 + 1] * inv1;
        f1.z = oa1[d4 * 4 + 2] * inv1; f1.w = oa1[d4 * 4 + 3] * inv1;
        op0[d4] = f0;
        op1[d4] = f1;
    }
}

// ---------------------------------------------------------------------------
extern "C" void kernel_launch(void* const* d_in, const int* in_sizes, int n_in,
                              void* d_out, int out_size)
{
    const float* x  = (const float*)d_in[0];
    const float* Wq = (const float*)d_in[1];
    const float* Wk = (const float*)d_in[2];
    const float* Wv = (const float*)d_in[3];
    const float* Wp = (const float*)d_in[4];
    float* out = (float*)d_out;

    float *gq, *gk, *gv, *go;
    cudaGetSymbolAddress((void**)&gq, g_q);
    cudaGetSymbolAddress((void**)&gk, g_k);
    cudaGetSymbolAddress((void**)&gv, g_v);
    cudaGetSymbolAddress((void**)&go, g_o);

    // QKV projections: [8192,768] @ [768,384] -> [B,H,N,32]
    dim3 gProj(HR_ / 64, M_ / 128);
    sgemm_kernel<<<gProj, 256>>>(x, Wq, gq, M_, C_, HR_, 1);
    sgemm_kernel<<<gProj, 256>>>(x, Wk, gk, M_, C_, HR_, 1);
    sgemm_kernel<<<gProj, 256>>>(x, Wv, gv, M_, C_, HR_, 1);

    // attention
    dim3 gAttn(N_ / 256, B_ * H_);
    attn_kernel<<<gAttn, 128>>>(gq, gk, gv, go);

    // output projection: [8192,384] @ [384,768] -> d_out
    dim3 gOut(C_ / 64, M_ / 128);
    sgemm_kernel<<<gOut, 256>>>(go, Wp, out, M_, HR_, C_, 0);
}

// round 3
// speedup vs baseline: 1.8210x; 1.6345x over previous
#include <cuda_runtime.h>

#define B_ 4
#define N_ 2048
#define C_ 768
#define H_ 12
#define R_ 32
#define M_ (B_ * N_)          // 8192 rows
#define HR_ (H_ * R_)         // 384

// Scratch (device globals; no allocations allowed)
__device__ float g_q[B_ * H_ * N_ * R_];
__device__ float g_k[B_ * H_ * N_ * R_];
__device__ float g_v[B_ * H_ * N_ * R_];
__device__ float g_o[B_ * N_ * HR_];

// ---------------------------------------------------------------------------
// Tiled SGEMM (unchanged from R2): C = A[M,K] @ W[K,Nc]
// ---------------------------------------------------------------------------
__global__ __launch_bounds__(256) void sgemm_kernel(
    const float* __restrict__ A, const float* __restrict__ W,
    float* __restrict__ Cout, int M, int K, int Nc, int mode)
{
    __shared__ float As[16][128];
    __shared__ float Ws[16][64];

    const int tid = threadIdx.x;
    const int tx = tid & 15;
    const int ty = tid >> 4;
    const int rowBase = blockIdx.y * 128;
    const int colBase = blockIdx.x * 64;

    const int ar = tid >> 1;
    const int ak = (tid & 1) * 8;
    const int wk = tid >> 4;
    const int wn = (tid & 15) * 4;

    const float* Aptr = A + (size_t)(rowBase + ar) * K + ak;
    const float* Wptr = W + (size_t)wk * Nc + colBase + wn;

    float acc[8][4] = {};

    for (int k0 = 0; k0 < K; k0 += 16) {
        float4 av0 = *(const float4*)(Aptr + k0);
        float4 av1 = *(const float4*)(Aptr + k0 + 4);
        float4 wv  = *(const float4*)(Wptr + (size_t)k0 * Nc);

        __syncthreads();
        As[ak + 0][ar] = av0.x; As[ak + 1][ar] = av0.y;
        As[ak + 2][ar] = av0.z; As[ak + 3][ar] = av0.w;
        As[ak + 4][ar] = av1.x; As[ak + 5][ar] = av1.y;
        As[ak + 6][ar] = av1.z; As[ak + 7][ar] = av1.w;
        *(float4*)&Ws[wk][wn] = wv;
        __syncthreads();

#pragma unroll
        for (int kk = 0; kk < 16; kk++) {
            float4 a0 = *(const float4*)&As[kk][ty * 8];
            float4 a1 = *(const float4*)&As[kk][ty * 8 + 4];
            float4 w  = *(const float4*)&Ws[kk][tx * 4];
            acc[0][0] += a0.x * w.x; acc[0][1] += a0.x * w.y; acc[0][2] += a0.x * w.z; acc[0][3] += a0.x * w.w;
            acc[1][0] += a0.y * w.x; acc[1][1] += a0.y * w.y; acc[1][2] += a0.y * w.z; acc[1][3] += a0.y * w.w;
            acc[2][0] += a0.z * w.x; acc[2][1] += a0.z * w.y; acc[2][2] += a0.z * w.z; acc[2][3] += a0.z * w.w;
            acc[3][0] += a0.w * w.x; acc[3][1] += a0.w * w.y; acc[3][2] += a0.w * w.z; acc[3][3] += a0.w * w.w;
            acc[4][0] += a1.x * w.x; acc[4][1] += a1.x * w.y; acc[4][2] += a1.x * w.z; acc[4][3] += a1.x * w.w;
            acc[5][0] += a1.y * w.x; acc[5][1] += a1.y * w.y; acc[5][2] += a1.y * w.z; acc[5][3] += a1.y * w.w;
            acc[6][0] += a1.z * w.x; acc[6][1] += a1.z * w.y; acc[6][2] += a1.z * w.z; acc[6][3] += a1.z * w.w;
            acc[7][0] += a1.w * w.x; acc[7][1] += a1.w * w.y; acc[7][2] += a1.w * w.z; acc[7][3] += a1.w * w.w;
        }
    }

#pragma unroll
    for (int i = 0; i < 8; i++) {
#pragma unroll
        for (int j = 0; j < 4; j++) {
            int row = rowBase + ty * 8 + i;
            int col = colBase + tx * 4 + j;
            if (mode == 0) {
                Cout[(size_t)row * Nc + col] = acc[i][j];
            } else {
                int b = row >> 11;
                int n = row & (N_ - 1);
                int h = col >> 5;
                int rr = col & (R_ - 1);
                Cout[((((size_t)b * H_ + h) * N_) + n) * R_ + rr] = acc[i][j];
            }
        }
    }
}

// ---------------------------------------------------------------------------
// Tensor-core flash attention (mma.sync m16n8k8 tf32).
// Block = 128 threads (4 warps). Q tile = 64 rows (16/warp). Key tile = 64.
// Softmax in exp2 domain; scale*log2e folded into Q.
// ---------------------------------------------------------------------------
__device__ __forceinline__ unsigned f2tf(float f) {
    unsigned u; asm("cvt.rna.tf32.f32 %0, %1;" : "=r"(u) : "f"(f)); return u;
}
__device__ __forceinline__ float ex2(float x) {
    float r; asm("ex2.approx.ftz.f32 %0, %1;" : "=f"(r) : "f"(x)); return r;
}
__device__ __forceinline__ void mma_tf32(float* c, unsigned a0, unsigned a1,
                                         unsigned a2, unsigned a3,
                                         unsigned b0, unsigned b1) {
    asm("mma.sync.aligned.m16n8k8.row.col.f32.tf32.tf32.f32 "
        "{%0,%1,%2,%3},{%4,%5,%6,%7},{%8,%9},{%0,%1,%2,%3};"
        : "+f"(c[0]), "+f"(c[1]), "+f"(c[2]), "+f"(c[3])
        : "r"(a0), "r"(a1), "r"(a2), "r"(a3), "r"(b0), "r"(b1));
}

#define KT_STRIDE 72   // Kt[32][72]  banks (8*tg + g) -> conflict-free B frags
#define VS_STRIDE 40   // Vs[64][40]  banks (8*tg + g) -> conflict-free B frags
#define PS_STRIDE 68   // Ps[64][68]  banks (4*g + tg) -> conflict-free A frags

__global__ __launch_bounds__(128) void attn_tc_kernel(
    const float* __restrict__ q, const float* __restrict__ k,
    const float* __restrict__ v, float* __restrict__ o)
{
    __shared__ unsigned Kt[32][KT_STRIDE];   // [r][key], tf32
    __shared__ unsigned Vs[64][VS_STRIDE];   // [key][vr], tf32
    __shared__ unsigned Ps[64][PS_STRIDE];   // [qrow][key], tf32

    const int tid  = threadIdx.x;
    const int w    = tid >> 5;        // warp 0..3
    const int lane = tid & 31;
    const int g    = lane >> 2;       // group 0..7
    const int tg   = lane & 3;        // 0..3
    const int bh   = blockIdx.y;
    const int qbase = blockIdx.x * 64;

    const float qscale = 0.125f * 1.44269504f;   // head_dim^-0.5 * log2(e)

    // ---- load Q fragments (rows qbase + 16w + {g, g+8}), pre-scaled ----
    unsigned qa[4][4];
    {
        const float* q0 = q + ((size_t)bh * N_ + qbase + w * 16 + g) * R_;
        const float* q1 = q0 + 8 * R_;
#pragma unroll
        for (int ks = 0; ks < 4; ks++) {
            qa[ks][0] = f2tf(q0[ks * 8 + tg] * qscale);
            qa[ks][1] = f2tf(q1[ks * 8 + tg] * qscale);
            qa[ks][2] = f2tf(q0[ks * 8 + tg + 4] * qscale);
            qa[ks][3] = f2tf(q1[ks * 8 + tg + 4] * qscale);
        }
    }

    float m0 = -1e30f, m1 = -1e30f, l0 = 0.0f, l1 = 0.0f;
    float oacc[4][4] = {};

    const float4* kg = (const float4*)(k + (size_t)bh * N_ * R_);
    const float4* vg = (const float4*)(v + (size_t)bh * N_ * R_);

    // tile-load indexing: thread covers float4 idx {tid, tid+128, tid+256, tid+384}
    // idx -> key = idx>>3, r4 = (idx&7)*4
    // preload tile 0 into smem
#pragma unroll
    for (int j = 0; j < 4; j++) {
        int idx = tid + j * 128;
        int key = idx >> 3, r4 = (idx & 7) * 4;
        float4 kf = kg[idx];
        Kt[r4 + 0][key] = f2tf(kf.x); Kt[r4 + 1][key] = f2tf(kf.y);
        Kt[r4 + 2][key] = f2tf(kf.z); Kt[r4 + 3][key] = f2tf(kf.w);
        float4 vf = vg[idx];
        uint4 vu = { f2tf(vf.x), f2tf(vf.y), f2tf(vf.z), f2tf(vf.w) };
        *(uint4*)&Vs[key][r4] = vu;
    }
    __syncthreads();

    const int NT = N_ / 64;   // 32 key tiles
    for (int kt = 0; kt < NT; kt++) {
        // prefetch next tile to registers
        float4 kr[4], vr4[4];
        if (kt + 1 < NT) {
            int base = (kt + 1) * 512;
#pragma unroll
            for (int j = 0; j < 4; j++) {
                kr[j]  = kg[base + tid + j * 128];
                vr4[j] = vg[base + tid + j * 128];
            }
        }

        // ---- S = Q @ K^T (in exp2 domain) ----
        float s[8][4];
#pragma unroll
        for (int nt = 0; nt < 8; nt++) { s[nt][0]=0; s[nt][1]=0; s[nt][2]=0; s[nt][3]=0; }
#pragma unroll
        for (int nt = 0; nt < 8; nt++) {
#pragma unroll
            for (int ks = 0; ks < 4; ks++) {
                unsigned b0 = Kt[ks * 8 + tg][nt * 8 + g];
                unsigned b1 = Kt[ks * 8 + tg + 4][nt * 8 + g];
                mma_tf32(s[nt], qa[ks][0], qa[ks][1], qa[ks][2], qa[ks][3], b0, b1);
            }
        }

        // ---- online softmax ----
        float r0 = -1e30f, r1 = -1e30f;
#pragma unroll
        for (int nt = 0; nt < 8; nt++) {
            r0 = fmaxf(r0, fmaxf(s[nt][0], s[nt][1]));
            r1 = fmaxf(r1, fmaxf(s[nt][2], s[nt][3]));
        }
        r0 = fmaxf(r0, __shfl_xor_sync(0xffffffff, r0, 1));
        r0 = fmaxf(r0, __shfl_xor_sync(0xffffffff, r0, 2));
        r1 = fmaxf(r1, __shfl_xor_sync(0xffffffff, r1, 1));
        r1 = fmaxf(r1, __shfl_xor_sync(0xffffffff, r1, 2));

        float mn0 = fmaxf(m0, r0), mn1 = fmaxf(m1, r1);
        float al0 = ex2(m0 - mn0), al1 = ex2(m1 - mn1);
        m0 = mn0; m1 = mn1;
        l0 *= al0; l1 *= al1;
#pragma unroll
        for (int nt = 0; nt < 4; nt++) {
            oacc[nt][0] *= al0; oacc[nt][1] *= al0;
            oacc[nt][2] *= al1; oacc[nt][3] *= al1;
        }

        const int prow0 = w * 16 + g;
#pragma unroll
        for (int nt = 0; nt < 8; nt++) {
            float p0 = ex2(s[nt][0] - m0);
            float p1 = ex2(s[nt][1] - m0);
            float p2 = ex2(s[nt][2] - m1);
            float p3 = ex2(s[nt][3] - m1);
            l0 += p0 + p1;
            l1 += p2 + p3;
            // store P (tf32) to smem: cols {nt*8+2tg, +1}, rows {prow0, prow0+8}
            unsigned long long u01 = (unsigned long long)f2tf(p0) |
                                     ((unsigned long long)f2tf(p1) << 32);
            unsigned long long u23 = (unsigned long long)f2tf(p2) |
                                     ((unsigned long long)f2tf(p3) << 32);
            *(unsigned long long*)&Ps[prow0][nt * 8 + 2 * tg]     = u01;
            *(unsigned long long*)&Ps[prow0 + 8][nt * 8 + 2 * tg] = u23;
        }
        __syncwarp();

        // ---- O += P @ V ----
#pragma unroll
        for (int ks = 0; ks < 8; ks++) {
            unsigned a0 = Ps[w * 16 + g][ks * 8 + tg];
            unsigned a1 = Ps[w * 16 + g + 8][ks * 8 + tg];
            unsigned a2 = Ps[w * 16 + g][ks * 8 + tg + 4];
            unsigned a3 = Ps[w * 16 + g + 8][ks * 8 + tg + 4];
#pragma unroll
            for (int nt = 0; nt < 4; nt++) {
                unsigned b0 = Vs[ks * 8 + tg][nt * 8 + g];
                unsigned b1 = Vs[ks * 8 + tg + 4][nt * 8 + g];
                mma_tf32(oacc[nt], a0, a1, a2, a3, b0, b1);
            }
        }

        // ---- commit prefetched tile ----
        if (kt + 1 < NT) {
            __syncthreads();
#pragma unroll
            for (int j = 0; j < 4; j++) {
                int idx = tid + j * 128;
                int key = idx >> 3, r4 = (idx & 7) * 4;
                Kt[r4 + 0][key] = f2tf(kr[j].x); Kt[r4 + 1][key] = f2tf(kr[j].y);
                Kt[r4 + 2][key] = f2tf(kr[j].z); Kt[r4 + 3][key] = f2tf(kr[j].w);
                uint4 vu = { f2tf(vr4[j].x), f2tf(vr4[j].y), f2tf(vr4[j].z), f2tf(vr4[j].w) };
                *(uint4*)&Vs[key][r4] = vu;
            }
            __syncthreads();
        }
    }

    // ---- finalize: reduce l across quad, normalize, write ----
    l0 += __shfl_xor_sync(0xffffffff, l0, 1);
    l0 += __shfl_xor_sync(0xffffffff, l0, 2);
    l1 += __shfl_xor_sync(0xffffffff, l1, 1);
    l1 += __shfl_xor_sync(0xffffffff, l1, 2);
    const float inv0 = 1.0f / l0;
    const float inv1 = 1.0f / l1;

    const int b = bh / H_;
    const int h = bh % H_;
    const int row0 = qbase + w * 16 + g;
    const int row1 = row0 + 8;
    float* o0 = o + (((size_t)b * N_ + row0) * H_ + h) * R_;
    float* o1 = o + (((size_t)b * N_ + row1) * H_ + h) * R_;
#pragma unroll
    for (int nt = 0; nt < 4; nt++) {
        int col = nt * 8 + 2 * tg;
        float2 f0 = { oacc[nt][0] * inv0, oacc[nt][1] * inv0 };
        float2 f1 = { oacc[nt][2] * inv1, oacc[nt][3] * inv1 };
        *(float2*)(o0 + col) = f0;
        *(float2*)(o1 + col) = f1;
    }
}

// ---------------------------------------------------------------------------
extern "C" void kernel_launch(void* const* d_in, const int* in_sizes, int n_in,
                              void* d_out, int out_size)
{
    const float* x  = (const float*)d_in[0];
    const float* Wq = (const float*)d_in[1];
    const float* Wk = (const float*)d_in[2];
    const float* Wv = (const float*)d_in[3];
    const float* Wp = (const float*)d_in[4];
    float* out = (float*)d_out;

    float *gq, *gk, *gv, *go;
    cudaGetSymbolAddress((void**)&gq, g_q);
    cudaGetSymbolAddress((void**)&gk, g_k);
    cudaGetSymbolAddress((void**)&gv, g_v);
    cudaGetSymbolAddress((void**)&go, g_o);

    // QKV projections: [8192,768] @ [768,384] -> [B,H,N,32]
    dim3 gProj(HR_ / 64, M_ / 128);
    sgemm_kernel<<<gProj, 256>>>(x, Wq, gq, M_, C_, HR_, 1);
    sgemm_kernel<<<gProj, 256>>>(x, Wk, gk, M_, C_, HR_, 1);
    sgemm_kernel<<<gProj, 256>>>(x, Wv, gv, M_, C_, HR_, 1);

    // attention (tensor-core)
    dim3 gAttn(N_ / 64, B_ * H_);
    attn_tc_kernel<<<gAttn, 128>>>(gq, gk, gv, go);

    // output projection: [8192,384] @ [384,768] -> d_out
    dim3 gOut(C_ / 64, M_ / 128);
    sgemm_kernel<<<gOut, 256>>>(go, Wp, out, M_, HR_, C_, 0);
}

// round 4
// speedup vs baseline: 2.3190x; 1.2735x over previous
#include <cuda_runtime.h>

#define B_ 4
#define N_ 2048
#define C_ 768
#define H_ 12
#define R_ 32
#define M_ (B_ * N_)          // 8192 rows
#define HR_ (H_ * R_)         // 384

// Scratch (device globals; no allocations allowed)
__device__ float g_q[B_ * H_ * N_ * R_];
__device__ float g_k[B_ * H_ * N_ * R_];
__device__ float g_v[B_ * H_ * N_ * R_];
__device__ float g_o[B_ * N_ * HR_];

// ---------------------------------------------------------------------------
// Common tf32 helpers
// ---------------------------------------------------------------------------
__device__ __forceinline__ unsigned f2tf(float f) {
    unsigned u; asm("cvt.rna.tf32.f32 %0, %1;" : "=r"(u) : "f"(f)); return u;
}
__device__ __forceinline__ float ex2(float x) {
    float r; asm("ex2.approx.ftz.f32 %0, %1;" : "=f"(r) : "f"(x)); return r;
}
__device__ __forceinline__ void mma_tf32(float* c, unsigned a0, unsigned a1,
                                         unsigned a2, unsigned a3,
                                         unsigned b0, unsigned b1) {
    asm("mma.sync.aligned.m16n8k8.row.col.f32.tf32.tf32.f32 "
        "{%0,%1,%2,%3},{%4,%5,%6,%7},{%8,%9},{%0,%1,%2,%3};"
        : "+f"(c[0]), "+f"(c[1]), "+f"(c[2]), "+f"(c[3])
        : "r"(a0), "r"(a1), "r"(a2), "r"(a3), "r"(b0), "r"(b1));
}

// ---------------------------------------------------------------------------
// TF32 tensor-core GEMM: C = A[M,K] @ W[K,Nc]
// BM=128, BN=64, BK=32. 256 threads = 8 warps, warp grid 4x2,
// each warp owns 32x32 = 2x4 m16n8 fragments.
// mode 0: C row-major [M, Nc]; mode 1: scatter into [B, H, N_, R_].
// Smem strides: As stride 136 (%32==8), Ws stride 72 (%32==8) so the
// (tg*S + g) fragment access pattern covers all 32 banks.
// ---------------------------------------------------------------------------
#define AS_STRIDE 136
#define WS_STRIDE 72

__global__ __launch_bounds__(256) void gemm_tf32_kernel(
    const float* __restrict__ A, const float* __restrict__ W,
    float* __restrict__ Cout, int M, int K, int Nc, int mode)
{
    __shared__ unsigned As[32][AS_STRIDE];   // [k][m]
    __shared__ unsigned Ws[32][WS_STRIDE];   // [k][n]

    const int tid  = threadIdx.x;
    const int w    = tid >> 5;
    const int lane = tid & 31;
    const int g    = lane >> 2;     // 0..7
    const int tg   = lane & 3;      // 0..3
    const int wr   = w >> 1;        // 0..3  -> m offset
    const int wc   = w & 1;         // 0..1  -> n offset
    const int m0   = wr * 32;
    const int n0   = wc * 32;
    const int rowBase = blockIdx.y * 128;
    const int colBase = blockIdx.x * 64;

    float acc[2][4][4] = {};

    // A tile loads: idx = tid + j*256 -> row = idx>>3, k4 = (idx&7)*4  (j=0..3)
    // W tile loads: idx = tid + j*256 -> kr  = idx>>4, n4 = (idx&15)*4 (j=0..1)
    const int a_row = 0;  (void)a_row;
    float4 pa[4], pw[2];

#pragma unroll
    for (int j = 0; j < 4; j++) {
        int idx = tid + j * 256;
        pa[j] = *(const float4*)(A + (size_t)(rowBase + (idx >> 3)) * K + (idx & 7) * 4);
    }
#pragma unroll
    for (int j = 0; j < 2; j++) {
        int idx = tid + j * 256;
        pw[j] = *(const float4*)(W + (size_t)(idx >> 4) * Nc + colBase + (idx & 15) * 4);
    }
#pragma unroll
    for (int j = 0; j < 4; j++) {
        int idx = tid + j * 256;
        int row = idx >> 3, k4 = (idx & 7) * 4;
        As[k4 + 0][row] = f2tf(pa[j].x);
        As[k4 + 1][row] = f2tf(pa[j].y);
        As[k4 + 2][row] = f2tf(pa[j].z);
        As[k4 + 3][row] = f2tf(pa[j].w);
    }
#pragma unroll
    for (int j = 0; j < 2; j++) {
        int idx = tid + j * 256;
        int kr = idx >> 4, n4 = (idx & 15) * 4;
        uint4 u = { f2tf(pw[j].x), f2tf(pw[j].y), f2tf(pw[j].z), f2tf(pw[j].w) };
        *(uint4*)&Ws[kr][n4] = u;
    }
    __syncthreads();

    const int KT = K >> 5;   // K / 32
    for (int kt = 0; kt < KT; kt++) {
        if (kt + 1 < KT) {
            int kq = (kt + 1) * 32;
#pragma unroll
            for (int j = 0; j < 4; j++) {
                int idx = tid + j * 256;
                pa[j] = *(const float4*)(A + (size_t)(rowBase + (idx >> 3)) * K + kq + (idx & 7) * 4);
            }
#pragma unroll
            for (int j = 0; j < 2; j++) {
                int idx = tid + j * 256;
                pw[j] = *(const float4*)(W + (size_t)(kq + (idx >> 4)) * Nc + colBase + (idx & 15) * 4);
            }
        }

#pragma unroll
        for (int ks = 0; ks < 4; ks++) {
            const int kk = ks * 8;
            unsigned b0[4], b1[4];
#pragma unroll
            for (int ni = 0; ni < 4; ni++) {
                b0[ni] = Ws[kk + tg][n0 + ni * 8 + g];
                b1[ni] = Ws[kk + tg + 4][n0 + ni * 8 + g];
            }
#pragma unroll
            for (int mi = 0; mi < 2; mi++) {
                unsigned a0 = As[kk + tg][m0 + mi * 16 + g];
                unsigned a1 = As[kk + tg][m0 + mi * 16 + g + 8];
                unsigned a2 = As[kk + tg + 4][m0 + mi * 16 + g];
                unsigned a3 = As[kk + tg + 4][m0 + mi * 16 + g + 8];
#pragma unroll
                for (int ni = 0; ni < 4; ni++)
                    mma_tf32(acc[mi][ni], a0, a1, a2, a3, b0[ni], b1[ni]);
            }
        }

        if (kt + 1 < KT) {
            __syncthreads();
#pragma unroll
            for (int j = 0; j < 4; j++) {
                int idx = tid + j * 256;
                int row = idx >> 3, k4 = (idx & 7) * 4;
                As[k4 + 0][row] = f2tf(pa[j].x);
                As[k4 + 1][row] = f2tf(pa[j].y);
                As[k4 + 2][row] = f2tf(pa[j].z);
                As[k4 + 3][row] = f2tf(pa[j].w);
            }
#pragma unroll
            for (int j = 0; j < 2; j++) {
                int idx = tid + j * 256;
                int kr = idx >> 4, n4 = (idx & 15) * 4;
                uint4 u = { f2tf(pw[j].x), f2tf(pw[j].y), f2tf(pw[j].z), f2tf(pw[j].w) };
                *(uint4*)&Ws[kr][n4] = u;
            }
            __syncthreads();
        }
    }

    // epilogue: thread owns rows {g, g+8} of each m16 tile, col pair 2tg,2tg+1
#pragma unroll
    for (int mi = 0; mi < 2; mi++) {
        int row0 = rowBase + m0 + mi * 16 + g;
        int row1 = row0 + 8;
#pragma unroll
        for (int ni = 0; ni < 4; ni++) {
            int col = colBase + n0 + ni * 8 + 2 * tg;  // even
            float2 f0 = { acc[mi][ni][0], acc[mi][ni][1] };
            float2 f1 = { acc[mi][ni][2], acc[mi][ni][3] };
            if (mode == 0) {
                *(float2*)&Cout[(size_t)row0 * Nc + col] = f0;
                *(float2*)&Cout[(size_t)row1 * Nc + col] = f1;
            } else {
                int h = col >> 5, rr = col & (R_ - 1);   // pair stays in-head (col even)
                int b0r = row0 >> 11, n0r = row0 & (N_ - 1);
                int b1r = row1 >> 11, n1r = row1 & (N_ - 1);
                *(float2*)&Cout[((((size_t)b0r * H_ + h) * N_) + n0r) * R_ + rr] = f0;
                *(float2*)&Cout[((((size_t)b1r * H_ + h) * N_) + n1r) * R_ + rr] = f1;
            }
        }
    }
}

// ---------------------------------------------------------------------------
// Tensor-core flash attention (unchanged from R3).
// ---------------------------------------------------------------------------
#define KT_STRIDE 72
#define VS_STRIDE 40
#define PS_STRIDE 68

__global__ __launch_bounds__(128) void attn_tc_kernel(
    const float* __restrict__ q, const float* __restrict__ k,
    const float* __restrict__ v, float* __restrict__ o)
{
    __shared__ unsigned Kt[32][KT_STRIDE];
    __shared__ unsigned Vs[64][VS_STRIDE];
    __shared__ unsigned Ps[64][PS_STRIDE];

    const int tid  = threadIdx.x;
    const int w    = tid >> 5;
    const int lane = tid & 31;
    const int g    = lane >> 2;
    const int tg   = lane & 3;
    const int bh   = blockIdx.y;
    const int qbase = blockIdx.x * 64;

    const float qscale = 0.125f * 1.44269504f;

    unsigned qa[4][4];
    {
        const float* q0 = q + ((size_t)bh * N_ + qbase + w * 16 + g) * R_;
        const float* q1 = q0 + 8 * R_;
#pragma unroll
        for (int ks = 0; ks < 4; ks++) {
            qa[ks][0] = f2tf(q0[ks * 8 + tg] * qscale);
            qa[ks][1] = f2tf(q1[ks * 8 + tg] * qscale);
            qa[ks][2] = f2tf(q0[ks * 8 + tg + 4] * qscale);
            qa[ks][3] = f2tf(q1[ks * 8 + tg + 4] * qscale);
        }
    }

    float m0 = -1e30f, m1 = -1e30f, l0 = 0.0f, l1 = 0.0f;
    float oacc[4][4] = {};

    const float4* kg = (const float4*)(k + (size_t)bh * N_ * R_);
    const float4* vg = (const float4*)(v + (size_t)bh * N_ * R_);

#pragma unroll
    for (int j = 0; j < 4; j++) {
        int idx = tid + j * 128;
        int key = idx >> 3, r4 = (idx & 7) * 4;
        float4 kf = kg[idx];
        Kt[r4 + 0][key] = f2tf(kf.x); Kt[r4 + 1][key] = f2tf(kf.y);
        Kt[r4 + 2][key] = f2tf(kf.z); Kt[r4 + 3][key] = f2tf(kf.w);
        float4 vf = vg[idx];
        uint4 vu = { f2tf(vf.x), f2tf(vf.y), f2tf(vf.z), f2tf(vf.w) };
        *(uint4*)&Vs[key][r4] = vu;
    }
    __syncthreads();

    const int NT = N_ / 64;
    for (int kt = 0; kt < NT; kt++) {
        float4 kr[4], vr4[4];
        if (kt + 1 < NT) {
            int base = (kt + 1) * 512;
#pragma unroll
            for (int j = 0; j < 4; j++) {
                kr[j]  = kg[base + tid + j * 128];
                vr4[j] = vg[base + tid + j * 128];
            }
        }

        float s[8][4];
#pragma unroll
        for (int nt = 0; nt < 8; nt++) { s[nt][0]=0; s[nt][1]=0; s[nt][2]=0; s[nt][3]=0; }
#pragma unroll
        for (int nt = 0; nt < 8; nt++) {
#pragma unroll
            for (int ks = 0; ks < 4; ks++) {
                unsigned b0 = Kt[ks * 8 + tg][nt * 8 + g];
                unsigned b1 = Kt[ks * 8 + tg + 4][nt * 8 + g];
                mma_tf32(s[nt], qa[ks][0], qa[ks][1], qa[ks][2], qa[ks][3], b0, b1);
            }
        }

        float r0 = -1e30f, r1 = -1e30f;
#pragma unroll
        for (int nt = 0; nt < 8; nt++) {
            r0 = fmaxf(r0, fmaxf(s[nt][0], s[nt][1]));
            r1 = fmaxf(r1, fmaxf(s[nt][2], s[nt][3]));
        }
        r0 = fmaxf(r0, __shfl_xor_sync(0xffffffff, r0, 1));
        r0 = fmaxf(r0, __shfl_xor_sync(0xffffffff, r0, 2));
        r1 = fmaxf(r1, __shfl_xor_sync(0xffffffff, r1, 1));
        r1 = fmaxf(r1, __shfl_xor_sync(0xffffffff, r1, 2));

        float mn0 = fmaxf(m0, r0), mn1 = fmaxf(m1, r1);
        float al0 = ex2(m0 - mn0), al1 = ex2(m1 - mn1);
        m0 = mn0; m1 = mn1;
        l0 *= al0; l1 *= al1;
#pragma unroll
        for (int nt = 0; nt < 4; nt++) {
            oacc[nt][0] *= al0; oacc[nt][1] *= al0;
            oacc[nt][2] *= al1; oacc[nt][3] *= al1;
        }

        const int prow0 = w * 16 + g;
#pragma unroll
        for (int nt = 0; nt < 8; nt++) {
            float p0 = ex2(s[nt][0] - m0);
            float p1 = ex2(s[nt][1] - m0);
            float p2 = ex2(s[nt][2] - m1);
            float p3 = ex2(s[nt][3] - m1);
            l0 += p0 + p1;
            l1 += p2 + p3;
            unsigned long long u01 = (unsigned long long)f2tf(p0) |
                                     ((unsigned long long)f2tf(p1) << 32);
            unsigned long long u23 = (unsigned long long)f2tf(p2) |
                                     ((unsigned long long)f2tf(p3) << 32);
            *(unsigned long long*)&Ps[prow0][nt * 8 + 2 * tg]     = u01;
            *(unsigned long long*)&Ps[prow0 + 8][nt * 8 + 2 * tg] = u23;
        }
        __syncwarp();

#pragma unroll
        for (int ks = 0; ks < 8; ks++) {
            unsigned a0 = Ps[w * 16 + g][ks * 8 + tg];
            unsigned a1 = Ps[w * 16 + g + 8][ks * 8 + tg];
            unsigned a2 = Ps[w * 16 + g][ks * 8 + tg + 4];
            unsigned a3 = Ps[w * 16 + g + 8][ks * 8 + tg + 4];
#pragma unroll
            for (int nt = 0; nt < 4; nt++) {
                unsigned b0 = Vs[ks * 8 + tg][nt * 8 + g];
                unsigned b1 = Vs[ks * 8 + tg + 4][nt * 8 + g];
                mma_tf32(oacc[nt], a0, a1, a2, a3, b0, b1);
            }
        }

        if (kt + 1 < NT) {
            __syncthreads();
#pragma unroll
            for (int j = 0; j < 4; j++) {
                int idx = tid + j * 128;
                int key = idx >> 3, r4 = (idx & 7) * 4;
                Kt[r4 + 0][key] = f2tf(kr[j].x); Kt[r4 + 1][key] = f2tf(kr[j].y);
                Kt[r4 + 2][key] = f2tf(kr[j].z); Kt[r4 + 3][key] = f2tf(kr[j].w);
                uint4 vu = { f2tf(vr4[j].x), f2tf(vr4[j].y), f2tf(vr4[j].z), f2tf(vr4[j].w) };
                *(uint4*)&Vs[key][r4] = vu;
            }
            __syncthreads();
        }
    }

    l0 += __shfl_xor_sync(0xffffffff, l0, 1);
    l0 += __shfl_xor_sync(0xffffffff, l0, 2);
    l1 += __shfl_xor_sync(0xffffffff, l1, 1);
    l1 += __shfl_xor_sync(0xffffffff, l1, 2);
    const float inv0 = 1.0f / l0;
    const float inv1 = 1.0f / l1;

    const int b = bh / H_;
    const int h = bh % H_;
    const int row0 = qbase + w * 16 + g;
    const int row1 = row0 + 8;
    float* o0 = o + (((size_t)b * N_ + row0) * H_ + h) * R_;
    float* o1 = o + (((size_t)b * N_ + row1) * H_ + h) * R_;
#pragma unroll
    for (int nt = 0; nt < 4; nt++) {
        int col = nt * 8 + 2 * tg;
        float2 f0 = { oacc[nt][0] * inv0, oacc[nt][1] * inv0 };
        float2 f1 = { oacc[nt][2] * inv1, oacc[nt][3] * inv1 };
        *(float2*)(o0 + col) = f0;
        *(float2*)(o1 + col) = f1;
    }
}

// ---------------------------------------------------------------------------
extern "C" void kernel_launch(void* const* d_in, const int* in_sizes, int n_in,
                              void* d_out, int out_size)
{
    const float* x  = (const float*)d_in[0];
    const float* Wq = (const float*)d_in[1];
    const float* Wk = (const float*)d_in[2];
    const float* Wv = (const float*)d_in[3];
    const float* Wp = (const float*)d_in[4];
    float* out = (float*)d_out;

    float *gq, *gk, *gv, *go;
    cudaGetSymbolAddress((void**)&gq, g_q);
    cudaGetSymbolAddress((void**)&gk, g_k);
    cudaGetSymbolAddress((void**)&gv, g_v);
    cudaGetSymbolAddress((void**)&go, g_o);

    // QKV projections: [8192,768] @ [768,384] -> [B,H,N,32]  (tensor core)
    dim3 gProj(HR_ / 64, M_ / 128);
    gemm_tf32_kernel<<<gProj, 256>>>(x, Wq, gq, M_, C_, HR_, 1);
    gemm_tf32_kernel<<<gProj, 256>>>(x, Wk, gk, M_, C_, HR_, 1);
    gemm_tf32_kernel<<<gProj, 256>>>(x, Wv, gv, M_, C_, HR_, 1);

    // attention (tensor core)
    dim3 gAttn(N_ / 64, B_ * H_);
    attn_tc_kernel<<<gAttn, 128>>>(gq, gk, gv, go);

    // output projection: [8192,384] @ [384,768] -> d_out  (tensor core)
    dim3 gOut(C_ / 64, M_ / 128);
    gemm_tf32_kernel<<<gOut, 256>>>(go, Wp, out, M_, HR_, C_, 0);
}

// round 5
// speedup vs baseline: 2.7248x; 1.1750x over previous
#include <cuda_runtime.h>

#define B_ 4
#define N_ 2048
#define C_ 768
#define H_ 12
#define R_ 32
#define M_ (B_ * N_)          // 8192 rows
#define HR_ (H_ * R_)         // 384

#define QSCALE (0.125f * 1.44269504f)   // head_dim^-0.5 * log2(e)

// Scratch (device globals; no allocations allowed)
// q/k/v hold tf32-bit patterns (q pre-scaled by QSCALE)
__device__ unsigned g_q[B_ * H_ * N_ * R_];
__device__ unsigned g_k[B_ * H_ * N_ * R_];
__device__ unsigned g_v[B_ * H_ * N_ * R_];
__device__ float    g_o[B_ * N_ * HR_];

// ---------------------------------------------------------------------------
// Common tf32 helpers
// ---------------------------------------------------------------------------
__device__ __forceinline__ unsigned f2tf(float f) {
    unsigned u; asm("cvt.rna.tf32.f32 %0, %1;" : "=r"(u) : "f"(f)); return u;
}
__device__ __forceinline__ float ex2(float x) {
    float r; asm("ex2.approx.ftz.f32 %0, %1;" : "=f"(r) : "f"(x)); return r;
}
__device__ __forceinline__ void mma_tf32(float* c, unsigned a0, unsigned a1,
                                         unsigned a2, unsigned a3,
                                         unsigned b0, unsigned b1) {
    asm("mma.sync.aligned.m16n8k8.row.col.f32.tf32.tf32.f32 "
        "{%0,%1,%2,%3},{%4,%5,%6,%7},{%8,%9},{%0,%1,%2,%3};"
        : "+f"(c[0]), "+f"(c[1]), "+f"(c[2]), "+f"(c[3])
        : "r"(a0), "r"(a1), "r"(a2), "r"(a3), "r"(b0), "r"(b1));
}

// ---------------------------------------------------------------------------
// TF32 tensor-core GEMM core. BM=128, BN=64, BK=32, 256 thr, 8 warps (4x2),
// warp tile 32x32 (2x4 m16n8 frags).
// MODE 0: float row-major out. MODE 1: scatter tf32-bits into [B,H,N,R]
//         (with optional scale folded pre-conversion).
// ---------------------------------------------------------------------------
#define AS_STRIDE 136
#define WS_STRIDE 72

template <int MODE>
__device__ __forceinline__ void gemm_tf32_body(
    const float* __restrict__ A, const float* __restrict__ W,
    void* __restrict__ CoutV, int K, int Nc, int rowBase, int colBase,
    float oscale)
{
    __shared__ unsigned As[32][AS_STRIDE];
    __shared__ unsigned Ws[32][WS_STRIDE];

    const int tid  = threadIdx.x;
    const int w    = tid >> 5;
    const int lane = tid & 31;
    const int g    = lane >> 2;
    const int tg   = lane & 3;
    const int m0   = (w >> 1) * 32;
    const int n0   = (w & 1) * 32;

    float acc[2][4][4] = {};
    float4 pa[4], pw[2];

#pragma unroll
    for (int j = 0; j < 4; j++) {
        int idx = tid + j * 256;
        pa[j] = *(const float4*)(A + (size_t)(rowBase + (idx >> 3)) * K + (idx & 7) * 4);
    }
#pragma unroll
    for (int j = 0; j < 2; j++) {
        int idx = tid + j * 256;
        pw[j] = *(const float4*)(W + (size_t)(idx >> 4) * Nc + colBase + (idx & 15) * 4);
    }
#pragma unroll
    for (int j = 0; j < 4; j++) {
        int idx = tid + j * 256;
        int row = idx >> 3, k4 = (idx & 7) * 4;
        As[k4 + 0][row] = f2tf(pa[j].x);
        As[k4 + 1][row] = f2tf(pa[j].y);
        As[k4 + 2][row] = f2tf(pa[j].z);
        As[k4 + 3][row] = f2tf(pa[j].w);
    }
#pragma unroll
    for (int j = 0; j < 2; j++) {
        int idx = tid + j * 256;
        int kr = idx >> 4, n4 = (idx & 15) * 4;
        uint4 u = { f2tf(pw[j].x), f2tf(pw[j].y), f2tf(pw[j].z), f2tf(pw[j].w) };
        *(uint4*)&Ws[kr][n4] = u;
    }
    __syncthreads();

    const int KT = K >> 5;
    for (int kt = 0; kt < KT; kt++) {
        if (kt + 1 < KT) {
            int kq = (kt + 1) * 32;
#pragma unroll
            for (int j = 0; j < 4; j++) {
                int idx = tid + j * 256;
                pa[j] = *(const float4*)(A + (size_t)(rowBase + (idx >> 3)) * K + kq + (idx & 7) * 4);
            }
#pragma unroll
            for (int j = 0; j < 2; j++) {
                int idx = tid + j * 256;
                pw[j] = *(const float4*)(W + (size_t)(kq + (idx >> 4)) * Nc + colBase + (idx & 15) * 4);
            }
        }

#pragma unroll
        for (int ks = 0; ks < 4; ks++) {
            const int kk = ks * 8;
            unsigned b0[4], b1[4];
#pragma unroll
            for (int ni = 0; ni < 4; ni++) {
                b0[ni] = Ws[kk + tg][n0 + ni * 8 + g];
                b1[ni] = Ws[kk + tg + 4][n0 + ni * 8 + g];
            }
#pragma unroll
            for (int mi = 0; mi < 2; mi++) {
                unsigned a0 = As[kk + tg][m0 + mi * 16 + g];
                unsigned a1 = As[kk + tg][m0 + mi * 16 + g + 8];
                unsigned a2 = As[kk + tg + 4][m0 + mi * 16 + g];
                unsigned a3 = As[kk + tg + 4][m0 + mi * 16 + g + 8];
#pragma unroll
                for (int ni = 0; ni < 4; ni++)
                    mma_tf32(acc[mi][ni], a0, a1, a2, a3, b0[ni], b1[ni]);
            }
        }

        if (kt + 1 < KT) {
            __syncthreads();
#pragma unroll
            for (int j = 0; j < 4; j++) {
                int idx = tid + j * 256;
                int row = idx >> 3, k4 = (idx & 7) * 4;
                As[k4 + 0][row] = f2tf(pa[j].x);
                As[k4 + 1][row] = f2tf(pa[j].y);
                As[k4 + 2][row] = f2tf(pa[j].z);
                As[k4 + 3][row] = f2tf(pa[j].w);
            }
#pragma unroll
            for (int j = 0; j < 2; j++) {
                int idx = tid + j * 256;
                int kr = idx >> 4, n4 = (idx & 15) * 4;
                uint4 u = { f2tf(pw[j].x), f2tf(pw[j].y), f2tf(pw[j].z), f2tf(pw[j].w) };
                *(uint4*)&Ws[kr][n4] = u;
            }
            __syncthreads();
        }
    }

#pragma unroll
    for (int mi = 0; mi < 2; mi++) {
        int row0 = rowBase + m0 + mi * 16 + g;
        int row1 = row0 + 8;
#pragma unroll
        for (int ni = 0; ni < 4; ni++) {
            int col = colBase + n0 + ni * 8 + 2 * tg;
            if (MODE == 0) {
                float* Cout = (float*)CoutV;
                float2 f0 = { acc[mi][ni][0], acc[mi][ni][1] };
                float2 f1 = { acc[mi][ni][2], acc[mi][ni][3] };
                *(float2*)&Cout[(size_t)row0 * Nc + col] = f0;
                *(float2*)&Cout[(size_t)row1 * Nc + col] = f1;
            } else {
                unsigned* Cout = (unsigned*)CoutV;
                int h = col >> 5, rr = col & (R_ - 1);
                int b0r = row0 >> 11, n0r = row0 & (N_ - 1);
                int b1r = row1 >> 11, n1r = row1 & (N_ - 1);
                uint2 u0 = { f2tf(acc[mi][ni][0] * oscale), f2tf(acc[mi][ni][1] * oscale) };
                uint2 u1 = { f2tf(acc[mi][ni][2] * oscale), f2tf(acc[mi][ni][3] * oscale) };
                *(uint2*)&Cout[((((size_t)b0r * H_ + h) * N_) + n0r) * R_ + rr] = u0;
                *(uint2*)&Cout[((((size_t)b1r * H_ + h) * N_) + n1r) * R_ + rr] = u1;
            }
        }
    }
}

// Fused QKV projection: grid.z selects (q|k|v). Output = tf32 bits, q scaled.
__global__ __launch_bounds__(256) void qkv_proj_kernel(
    const float* __restrict__ x,
    const float* __restrict__ Wq, const float* __restrict__ Wk,
    const float* __restrict__ Wv,
    unsigned* __restrict__ oq, unsigned* __restrict__ ok,
    unsigned* __restrict__ ov)
{
    const int z = blockIdx.z;
    const float* W = (z == 0) ? Wq : (z == 1) ? Wk : Wv;
    unsigned* out  = (z == 0) ? oq : (z == 1) ? ok : ov;
    float scl      = (z == 0) ? QSCALE : 1.0f;
    gemm_tf32_body<1>(x, W, out, C_, HR_, blockIdx.y * 128, blockIdx.x * 64, scl);
}

// Final projection: float out, row-major.
__global__ __launch_bounds__(256) void out_proj_kernel(
    const float* __restrict__ A, const float* __restrict__ W,
    float* __restrict__ Cout)
{
    gemm_tf32_body<0>(A, W, Cout, HR_, C_, blockIdx.y * 128, blockIdx.x * 64, 1.0f);
}

// ---------------------------------------------------------------------------
// Tensor-core flash attention, 32 q-rows per warp (q-block 128, 4 warps).
// Inputs are pre-converted tf32 bits (q pre-scaled). B-fragments loaded once
// and reused for both m16 row tiles. Dynamic smem (54.3KB).
// ---------------------------------------------------------------------------
#define KT_STRIDE 72
#define VS_STRIDE 40
#define PS_STRIDE 68
#define SMEM_ATTN ((32 * KT_STRIDE + 64 * VS_STRIDE + 128 * PS_STRIDE) * 4)

__global__ __launch_bounds__(128) void attn_tc_kernel(
    const unsigned* __restrict__ q, const unsigned* __restrict__ k,
    const unsigned* __restrict__ v, float* __restrict__ o)
{
    extern __shared__ unsigned smem[];
    unsigned (*Kt)[KT_STRIDE] = (unsigned(*)[KT_STRIDE])smem;                        // [r][key]
    unsigned (*Vs)[VS_STRIDE] = (unsigned(*)[VS_STRIDE])(smem + 32 * KT_STRIDE);     // [key][r]
    unsigned (*Ps)[PS_STRIDE] = (unsigned(*)[PS_STRIDE])(smem + 32 * KT_STRIDE + 64 * VS_STRIDE); // [qrow][key]

    const int tid  = threadIdx.x;
    const int w    = tid >> 5;
    const int lane = tid & 31;
    const int g    = lane >> 2;
    const int tg   = lane & 3;
    const int bh   = blockIdx.y;
    const int qbase = blockIdx.x * 128;

    // ---- Q fragments: rows qbase + w*32 + mi*16 + {g, g+8} (already tf32+scaled)
    unsigned qa[2][4][4];
#pragma unroll
    for (int mi = 0; mi < 2; mi++) {
        const unsigned* q0 = q + ((size_t)bh * N_ + qbase + w * 32 + mi * 16 + g) * R_;
        const unsigned* q1 = q0 + 8 * R_;
#pragma unroll
        for (int ks = 0; ks < 4; ks++) {
            qa[mi][ks][0] = q0[ks * 8 + tg];
            qa[mi][ks][1] = q1[ks * 8 + tg];
            qa[mi][ks][2] = q0[ks * 8 + tg + 4];
            qa[mi][ks][3] = q1[ks * 8 + tg + 4];
        }
    }

    float m[2][2] = { {-1e30f, -1e30f}, {-1e30f, -1e30f} };
    float l[2][2] = {};
    float oacc[2][4][4] = {};

    const uint4* kg = (const uint4*)(k + (size_t)bh * N_ * R_);
    const uint4* vg = (const uint4*)(v + (size_t)bh * N_ * R_);

    // preload tile 0 (no converts; data already tf32)
#pragma unroll
    for (int j = 0; j < 4; j++) {
        int idx = tid + j * 128;
        int key = idx >> 3, r4 = (idx & 7) * 4;
        uint4 kf = kg[idx];
        Kt[r4 + 0][key] = kf.x; Kt[r4 + 1][key] = kf.y;
        Kt[r4 + 2][key] = kf.z; Kt[r4 + 3][key] = kf.w;
        *(uint4*)&Vs[key][r4] = vg[idx];
    }
    __syncthreads();

    const int NT = N_ / 64;
    for (int kt = 0; kt < NT; kt++) {
        uint4 kr[4], vr[4];
        if (kt + 1 < NT) {
            int base = (kt + 1) * 512;
#pragma unroll
            for (int j = 0; j < 4; j++) {
                kr[j] = kg[base + tid + j * 128];
                vr[j] = vg[base + tid + j * 128];
            }
        }

        // ---- S = Q @ K^T: B-frags loaded once, used for both row tiles ----
        float s[2][8][4];
#pragma unroll
        for (int mi = 0; mi < 2; mi++)
#pragma unroll
            for (int nt = 0; nt < 8; nt++) {
                s[mi][nt][0] = 0; s[mi][nt][1] = 0; s[mi][nt][2] = 0; s[mi][nt][3] = 0;
            }
#pragma unroll
        for (int nt = 0; nt < 8; nt++) {
#pragma unroll
            for (int ks = 0; ks < 4; ks++) {
                unsigned b0 = Kt[ks * 8 + tg][nt * 8 + g];
                unsigned b1 = Kt[ks * 8 + tg + 4][nt * 8 + g];
                mma_tf32(s[0][nt], qa[0][ks][0], qa[0][ks][1], qa[0][ks][2], qa[0][ks][3], b0, b1);
                mma_tf32(s[1][nt], qa[1][ks][0], qa[1][ks][1], qa[1][ks][2], qa[1][ks][3], b0, b1);
            }
        }

        // ---- online softmax + P store (per row tile) ----
#pragma unroll
        for (int mi = 0; mi < 2; mi++) {
            float r0 = -1e30f, r1 = -1e30f;
#pragma unroll
            for (int nt = 0; nt < 8; nt++) {
                r0 = fmaxf(r0, fmaxf(s[mi][nt][0], s[mi][nt][1]));
                r1 = fmaxf(r1, fmaxf(s[mi][nt][2], s[mi][nt][3]));
            }
            r0 = fmaxf(r0, __shfl_xor_sync(0xffffffff, r0, 1));
            r0 = fmaxf(r0, __shfl_xor_sync(0xffffffff, r0, 2));
            r1 = fmaxf(r1, __shfl_xor_sync(0xffffffff, r1, 1));
            r1 = fmaxf(r1, __shfl_xor_sync(0xffffffff, r1, 2));

            float mn0 = fmaxf(m[mi][0], r0), mn1 = fmaxf(m[mi][1], r1);
            float al0 = ex2(m[mi][0] - mn0), al1 = ex2(m[mi][1] - mn1);
            m[mi][0] = mn0; m[mi][1] = mn1;
            l[mi][0] *= al0; l[mi][1] *= al1;
#pragma unroll
            for (int nt = 0; nt < 4; nt++) {
                oacc[mi][nt][0] *= al0; oacc[mi][nt][1] *= al0;
                oacc[mi][nt][2] *= al1; oacc[mi][nt][3] *= al1;
            }

            const int prow0 = w * 32 + mi * 16 + g;
#pragma unroll
            for (int nt = 0; nt < 8; nt++) {
                float p0 = ex2(s[mi][nt][0] - mn0);
                float p1 = ex2(s[mi][nt][1] - mn0);
                float p2 = ex2(s[mi][nt][2] - mn1);
                float p3 = ex2(s[mi][nt][3] - mn1);
                l[mi][0] += p0 + p1;
                l[mi][1] += p2 + p3;
                unsigned long long u01 = (unsigned long long)f2tf(p0) |
                                         ((unsigned long long)f2tf(p1) << 32);
                unsigned long long u23 = (unsigned long long)f2tf(p2) |
                                         ((unsigned long long)f2tf(p3) << 32);
                *(unsigned long long*)&Ps[prow0][nt * 8 + 2 * tg]     = u01;
                *(unsigned long long*)&Ps[prow0 + 8][nt * 8 + 2 * tg] = u23;
            }
        }
        __syncwarp();

        // ---- O += P @ V: B-frags loaded once per ks, reused for both tiles ----
#pragma unroll
        for (int ks = 0; ks < 8; ks++) {
            unsigned b0[4], b1[4];
#pragma unroll
            for (int nt = 0; nt < 4; nt++) {
                b0[nt] = Vs[ks * 8 + tg][nt * 8 + g];
                b1[nt] = Vs[ks * 8 + tg + 4][nt * 8 + g];
            }
#pragma unroll
            for (int mi = 0; mi < 2; mi++) {
                const int prow = w * 32 + mi * 16 + g;
                unsigned a0 = Ps[prow][ks * 8 + tg];
                unsigned a1 = Ps[prow + 8][ks * 8 + tg];
                unsigned a2 = Ps[prow][ks * 8 + tg + 4];
                unsigned a3 = Ps[prow + 8][ks * 8 + tg + 4];
#pragma unroll
                for (int nt = 0; nt < 4; nt++)
                    mma_tf32(oacc[mi][nt], a0, a1, a2, a3, b0[nt], b1[nt]);
            }
        }

        if (kt + 1 < NT) {
            __syncthreads();
#pragma unroll
            for (int j = 0; j < 4; j++) {
                int idx = tid + j * 128;
                int key = idx >> 3, r4 = (idx & 7) * 4;
                Kt[r4 + 0][key] = kr[j].x; Kt[r4 + 1][key] = kr[j].y;
                Kt[r4 + 2][key] = kr[j].z; Kt[r4 + 3][key] = kr[j].w;
                *(uint4*)&Vs[key][r4] = vr[j];
            }
            __syncthreads();
        }
    }

    // ---- finalize ----
    const int b = bh / H_;
    const int h = bh % H_;
#pragma unroll
    for (int mi = 0; mi < 2; mi++) {
        float l0 = l[mi][0], l1 = l[mi][1];
        l0 += __shfl_xor_sync(0xffffffff, l0, 1);
        l0 += __shfl_xor_sync(0xffffffff, l0, 2);
        l1 += __shfl_xor_sync(0xffffffff, l1, 1);
        l1 += __shfl_xor_sync(0xffffffff, l1, 2);
        const float inv0 = 1.0f / l0;
        const float inv1 = 1.0f / l1;

        const int row0 = qbase + w * 32 + mi * 16 + g;
        const int row1 = row0 + 8;
        float* o0 = o + (((size_t)b * N_ + row0) * H_ + h) * R_;
        float* o1 = o + (((size_t)b * N_ + row1) * H_ + h) * R_;
#pragma unroll
        for (int nt = 0; nt < 4; nt++) {
            int col = nt * 8 + 2 * tg;
            float2 f0 = { oacc[mi][nt][0] * inv0, oacc[mi][nt][1] * inv0 };
            float2 f1 = { oacc[mi][nt][2] * inv1, oacc[mi][nt][3] * inv1 };
            *(float2*)(o0 + col) = f0;
            *(float2*)(o1 + col) = f1;
        }
    }
}

// ---------------------------------------------------------------------------
extern "C" void kernel_launch(void* const* d_in, const int* in_sizes, int n_in,
                              void* d_out, int out_size)
{
    const float* x  = (const float*)d_in[0];
    const float* Wq = (const float*)d_in[1];
    const float* Wk = (const float*)d_in[2];
    const float* Wv = (const float*)d_in[3];
    const float* Wp = (const float*)d_in[4];
    float* out = (float*)d_out;

    unsigned *gq, *gk, *gv;
    float* go;
    cudaGetSymbolAddress((void**)&gq, g_q);
    cudaGetSymbolAddress((void**)&gk, g_k);
    cudaGetSymbolAddress((void**)&gv, g_v);
    cudaGetSymbolAddress((void**)&go, g_o);

    static bool attr_set = false;
    if (!attr_set) {
        cudaFuncSetAttribute(attn_tc_kernel,
                             cudaFuncAttributeMaxDynamicSharedMemorySize, SMEM_ATTN);
        attr_set = true;
    }

    // Fused QKV projections (tensor core, tf32-bit output, q pre-scaled)
    dim3 gProj(HR_ / 64, M_ / 128, 3);
    qkv_proj_kernel<<<gProj, 256>>>(x, Wq, Wk, Wv, gq, gk, gv);

    // attention (tensor core)
    dim3 gAttn(N_ / 128, B_ * H_);
    attn_tc_kernel<<<gAttn, 128, SMEM_ATTN>>>(gq, gk, gv, go);

    // output projection
    dim3 gOut(C_ / 64, M_ / 128);
    out_proj_kernel<<<gOut, 256>>>(go, Wp, out);
}

// round 7
// speedup vs baseline: 3.7566x; 1.3786x over previous
#include <cuda_runtime.h>

#define B_ 4
#define N_ 2048
#define C_ 768
#define H_ 12
#define R_ 32
#define M_ (B_ * N_)          // 8192 rows
#define HR_ (H_ * R_)         // 384

#define QSCALE (0.125f * 1.44269504f)   // head_dim^-0.5 * log2(e)

// Scratch (device globals; no allocations allowed)
// q/k/v hold tf32-bit patterns (q pre-scaled by QSCALE)
__device__ unsigned g_q[B_ * H_ * N_ * R_];
__device__ unsigned g_k[B_ * H_ * N_ * R_];
__device__ unsigned g_v[B_ * H_ * N_ * R_];
__device__ float    g_o[B_ * N_ * HR_];

// ---------------------------------------------------------------------------
// Common tf32 helpers
// ---------------------------------------------------------------------------
__device__ __forceinline__ unsigned f2tf(float f) {
    unsigned u; asm("cvt.rna.tf32.f32 %0, %1;" : "=r"(u) : "f"(f)); return u;
}
__device__ __forceinline__ float ex2(float x) {
    float r; asm("ex2.approx.ftz.f32 %0, %1;" : "=f"(r) : "f"(x)); return r;
}
__device__ __forceinline__ void mma_tf32(float* c, unsigned a0, unsigned a1,
                                         unsigned a2, unsigned a3,
                                         unsigned b0, unsigned b1) {
    asm("mma.sync.aligned.m16n8k8.row.col.f32.tf32.tf32.f32 "
        "{%0,%1,%2,%3},{%4,%5,%6,%7},{%8,%9},{%0,%1,%2,%3};"
        : "+f"(c[0]), "+f"(c[1]), "+f"(c[2]), "+f"(c[3])
        : "r"(a0), "r"(a1), "r"(a2), "r"(a3), "r"(b0), "r"(b1));
}

// ---------------------------------------------------------------------------
// TF32 tensor-core GEMM core. BM=128, BN=64, BK=32, 256 thr, 8 warps (4x2),
// warp tile 32x32 (2x4 m16n8 frags).
// A staged ROW-MAJOR As[row][k], stride 36 (== 4 mod 32):
//   - staging STS.128: per-phase lanes share a row, k4 spans banks -> clean
//   - frag loads: bank = 4g + tg (+8ks) -> all 32 banks -> clean
// W staged k-major Ws[k][n], stride 72 (== 8 mod 32): both paths clean.
// MODE 0: float row-major out. MODE 1: scatter tf32-bits into [B,H,N,R].
// ---------------------------------------------------------------------------
#define AS_STRIDE 36
#define WS_STRIDE 72

template <int MODE>
__device__ __forceinline__ void gemm_tf32_body(
    const float* __restrict__ A, const float* __restrict__ W,
    void* __restrict__ CoutV, int K, int Nc, int rowBase, int colBase,
    float oscale)
{
    __shared__ unsigned As[128][AS_STRIDE];   // [m][k]
    __shared__ unsigned Ws[32][WS_STRIDE];    // [k][n]

    const int tid  = threadIdx.x;
    const int w    = tid >> 5;
    const int lane = tid & 31;
    const int g    = lane >> 2;
    const int tg   = lane & 3;
    const int m0   = (w >> 1) * 32;
    const int n0   = (w & 1) * 32;

    float acc[2][4][4] = {};
    float4 pa[4], pw[2];

#pragma unroll
    for (int j = 0; j < 4; j++) {
        int idx = tid + j * 256;
        pa[j] = *(const float4*)(A + (size_t)(rowBase + (idx >> 3)) * K + (idx & 7) * 4);
    }
#pragma unroll
    for (int j = 0; j < 2; j++) {
        int idx = tid + j * 256;
        pw[j] = *(const float4*)(W + (size_t)(idx >> 4) * Nc + colBase + (idx & 15) * 4);
    }
#pragma unroll
    for (int j = 0; j < 4; j++) {
        int idx = tid + j * 256;
        int row = idx >> 3, k4 = (idx & 7) * 4;
        uint4 u = { f2tf(pa[j].x), f2tf(pa[j].y), f2tf(pa[j].z), f2tf(pa[j].w) };
        *(uint4*)&As[row][k4] = u;
    }
#pragma unroll
    for (int j = 0; j < 2; j++) {
        int idx = tid + j * 256;
        int kr = idx >> 4, n4 = (idx & 15) * 4;
        uint4 u = { f2tf(pw[j].x), f2tf(pw[j].y), f2tf(pw[j].z), f2tf(pw[j].w) };
        *(uint4*)&Ws[kr][n4] = u;
    }
    __syncthreads();

    const int KT = K >> 5;
    for (int kt = 0; kt < KT; kt++) {
        if (kt + 1 < KT) {
            int kq = (kt + 1) * 32;
#pragma unroll
            for (int j = 0; j < 4; j++) {
                int idx = tid + j * 256;
                pa[j] = *(const float4*)(A + (size_t)(rowBase + (idx >> 3)) * K + kq + (idx & 7) * 4);
            }
#pragma unroll
            for (int j = 0; j < 2; j++) {
                int idx = tid + j * 256;
                pw[j] = *(const float4*)(W + (size_t)(kq + (idx >> 4)) * Nc + colBase + (idx & 15) * 4);
            }
        }

#pragma unroll
        for (int ks = 0; ks < 4; ks++) {
            const int kk = ks * 8;
            unsigned b0[4], b1[4];
#pragma unroll
            for (int ni = 0; ni < 4; ni++) {
                b0[ni] = Ws[kk + tg][n0 + ni * 8 + g];
                b1[ni] = Ws[kk + tg + 4][n0 + ni * 8 + g];
            }
#pragma unroll
            for (int mi = 0; mi < 2; mi++) {
                unsigned a0 = As[m0 + mi * 16 + g][kk + tg];
                unsigned a1 = As[m0 + mi * 16 + g + 8][kk + tg];
                unsigned a2 = As[m0 + mi * 16 + g][kk + tg + 4];
                unsigned a3 = As[m0 + mi * 16 + g + 8][kk + tg + 4];
#pragma unroll
                for (int ni = 0; ni < 4; ni++)
                    mma_tf32(acc[mi][ni], a0, a1, a2, a3, b0[ni], b1[ni]);
            }
        }

        if (kt + 1 < KT) {
            __syncthreads();
#pragma unroll
            for (int j = 0; j < 4; j++) {
                int idx = tid + j * 256;
                int row = idx >> 3, k4 = (idx & 7) * 4;
                uint4 u = { f2tf(pa[j].x), f2tf(pa[j].y), f2tf(pa[j].z), f2tf(pa[j].w) };
                *(uint4*)&As[row][k4] = u;
            }
#pragma unroll
            for (int j = 0; j < 2; j++) {
                int idx = tid + j * 256;
                int kr = idx >> 4, n4 = (idx & 15) * 4;
                uint4 u = { f2tf(pw[j].x), f2tf(pw[j].y), f2tf(pw[j].z), f2tf(pw[j].w) };
                *(uint4*)&Ws[kr][n4] = u;
            }
            __syncthreads();
        }
    }

#pragma unroll
    for (int mi = 0; mi < 2; mi++) {
        int row0 = rowBase + m0 + mi * 16 + g;
        int row1 = row0 + 8;
#pragma unroll
        for (int ni = 0; ni < 4; ni++) {
            int col = colBase + n0 + ni * 8 + 2 * tg;
            if (MODE == 0) {
                float* Cout = (float*)CoutV;
                float2 f0 = { acc[mi][ni][0], acc[mi][ni][1] };
                float2 f1 = { acc[mi][ni][2], acc[mi][ni][3] };
                *(float2*)&Cout[(size_t)row0 * Nc + col] = f0;
                *(float2*)&Cout[(size_t)row1 * Nc + col] = f1;
            } else {
                unsigned* Cout = (unsigned*)CoutV;
                int h = col >> 5, rr = col & (R_ - 1);
                int b0r = row0 >> 11, n0r = row0 & (N_ - 1);
                int b1r = row1 >> 11, n1r = row1 & (N_ - 1);
                uint2 u0 = { f2tf(acc[mi][ni][0] * oscale), f2tf(acc[mi][ni][1] * oscale) };
                uint2 u1 = { f2tf(acc[mi][ni][2] * oscale), f2tf(acc[mi][ni][3] * oscale) };
                *(uint2*)&Cout[((((size_t)b0r * H_ + h) * N_) + n0r) * R_ + rr] = u0;
                *(uint2*)&Cout[((((size_t)b1r * H_ + h) * N_) + n1r) * R_ + rr] = u1;
            }
        }
    }
}

// Fused QKV projection: grid.z selects (q|k|v). Output = tf32 bits, q scaled.
__global__ __launch_bounds__(256) void qkv_proj_kernel(
    const float* __restrict__ x,
    const float* __restrict__ Wq, const float* __restrict__ Wk,
    const float* __restrict__ Wv,
    unsigned* __restrict__ oq, unsigned* __restrict__ ok,
    unsigned* __restrict__ ov)
{
    const int z = blockIdx.z;
    const float* W = (z == 0) ? Wq : (z == 1) ? Wk : Wv;
    unsigned* out  = (z == 0) ? oq : (z == 1) ? ok : ov;
    float scl      = (z == 0) ? QSCALE : 1.0f;
    gemm_tf32_body<1>(x, W, out, C_, HR_, blockIdx.y * 128, blockIdx.x * 64, scl);
}

// Final projection: float out, row-major.
__global__ __launch_bounds__(256) void out_proj_kernel(
    const float* __restrict__ A, const float* __restrict__ W,
    float* __restrict__ Cout)
{
    gemm_tf32_body<0>(A, W, Cout, HR_, C_, blockIdx.y * 128, blockIdx.x * 64, 1.0f);
}

// ---------------------------------------------------------------------------
// Tensor-core flash attention, 32 q-rows per warp (q-block 128, 4 warps).
// K/V stored ROW-MAJOR [key][r], stride 36/40 (transpose-free staging; both
// staging STS.128 and frag loads conflict-free).
// Ps[qrow][key]: rows must hold 64 keys -> stride 68 (== 4 mod 32; A-frag
// pattern 4g+tg+8ks covers all banks).
// ---------------------------------------------------------------------------
#define KS_STRIDE 36
#define VS_STRIDE 40
#define PS_STRIDE 68
#define SMEM_ATTN ((64 * KS_STRIDE + 64 * VS_STRIDE + 128 * PS_STRIDE) * 4)

__global__ __launch_bounds__(128) void attn_tc_kernel(
    const unsigned* __restrict__ q, const unsigned* __restrict__ k,
    const unsigned* __restrict__ v, float* __restrict__ o)
{
    extern __shared__ unsigned smem[];
    unsigned (*Ks)[KS_STRIDE] = (unsigned(*)[KS_STRIDE])smem;                        // [key][r]
    unsigned (*Vs)[VS_STRIDE] = (unsigned(*)[VS_STRIDE])(smem + 64 * KS_STRIDE);     // [key][r]
    unsigned (*Ps)[PS_STRIDE] = (unsigned(*)[PS_STRIDE])(smem + 64 * KS_STRIDE + 64 * VS_STRIDE); // [qrow][key]

    const int tid  = threadIdx.x;
    const int w    = tid >> 5;
    const int lane = tid & 31;
    const int g    = lane >> 2;
    const int tg   = lane & 3;
    const int bh   = blockIdx.y;
    const int qbase = blockIdx.x * 128;

    // ---- Q fragments (already tf32 + pre-scaled) ----
    unsigned qa[2][4][4];
#pragma unroll
    for (int mi = 0; mi < 2; mi++) {
        const unsigned* q0 = q + ((size_t)bh * N_ + qbase + w * 32 + mi * 16 + g) * R_;
        const unsigned* q1 = q0 + 8 * R_;
#pragma unroll
        for (int ks = 0; ks < 4; ks++) {
            qa[mi][ks][0] = q0[ks * 8 + tg];
            qa[mi][ks][1] = q1[ks * 8 + tg];
            qa[mi][ks][2] = q0[ks * 8 + tg + 4];
            qa[mi][ks][3] = q1[ks * 8 + tg + 4];
        }
    }

    float m[2][2] = { {-1e30f, -1e30f}, {-1e30f, -1e30f} };
    float l[2][2] = {};
    float oacc[2][4][4] = {};

    const uint4* kg = (const uint4*)(k + (size_t)bh * N_ * R_);
    const uint4* vg = (const uint4*)(v + (size_t)bh * N_ * R_);

    // preload tile 0: row-major stores, STS.128, conflict-free
#pragma unroll
    for (int j = 0; j < 4; j++) {
        int idx = tid + j * 128;
        int key = idx >> 3, r4 = (idx & 7) * 4;
        *(uint4*)&Ks[key][r4] = kg[idx];
        *(uint4*)&Vs[key][r4] = vg[idx];
    }
    __syncthreads();

    const int NT = N_ / 64;
    for (int kt = 0; kt < NT; kt++) {
        uint4 kr[4], vr[4];
        if (kt + 1 < NT) {
            int base = (kt + 1) * 512;
#pragma unroll
            for (int j = 0; j < 4; j++) {
                kr[j] = kg[base + tid + j * 128];
                vr[j] = vg[base + tid + j * 128];
            }
        }

        // ---- S = Q @ K^T ----
        float s[2][8][4];
#pragma unroll
        for (int mi = 0; mi < 2; mi++)
#pragma unroll
            for (int nt = 0; nt < 8; nt++) {
                s[mi][nt][0] = 0; s[mi][nt][1] = 0; s[mi][nt][2] = 0; s[mi][nt][3] = 0;
            }
#pragma unroll
        for (int nt = 0; nt < 8; nt++) {
#pragma unroll
            for (int ks = 0; ks < 4; ks++) {
                unsigned b0 = Ks[nt * 8 + g][ks * 8 + tg];
                unsigned b1 = Ks[nt * 8 + g][ks * 8 + tg + 4];
                mma_tf32(s[0][nt], qa[0][ks][0], qa[0][ks][1], qa[0][ks][2], qa[0][ks][3], b0, b1);
                mma_tf32(s[1][nt], qa[1][ks][0], qa[1][ks][1], qa[1][ks][2], qa[1][ks][3], b0, b1);
            }
        }

        // ---- online softmax + P store ----
#pragma unroll
        for (int mi = 0; mi < 2; mi++) {
            float r0 = -1e30f, r1 = -1e30f;
#pragma unroll
            for (int nt = 0; nt < 8; nt++) {
                r0 = fmaxf(r0, fmaxf(s[mi][nt][0], s[mi][nt][1]));
                r1 = fmaxf(r1, fmaxf(s[mi][nt][2], s[mi][nt][3]));
            }
            r0 = fmaxf(r0, __shfl_xor_sync(0xffffffff, r0, 1));
            r0 = fmaxf(r0, __shfl_xor_sync(0xffffffff, r0, 2));
            r1 = fmaxf(r1, __shfl_xor_sync(0xffffffff, r1, 1));
            r1 = fmaxf(r1, __shfl_xor_sync(0xffffffff, r1, 2));

            float mn0 = fmaxf(m[mi][0], r0), mn1 = fmaxf(m[mi][1], r1);
            float al0 = ex2(m[mi][0] - mn0), al1 = ex2(m[mi][1] - mn1);
            m[mi][0] = mn0; m[mi][1] = mn1;
            l[mi][0] *= al0; l[mi][1] *= al1;
#pragma unroll
            for (int nt = 0; nt < 4; nt++) {
                oacc[mi][nt][0] *= al0; oacc[mi][nt][1] *= al0;
                oacc[mi][nt][2] *= al1; oacc[mi][nt][3] *= al1;
            }

            const int prow0 = w * 32 + mi * 16 + g;
#pragma unroll
            for (int nt = 0; nt < 8; nt++) {
                float p0 = ex2(s[mi][nt][0] - mn0);
                float p1 = ex2(s[mi][nt][1] - mn0);
                float p2 = ex2(s[mi][nt][2] - mn1);
                float p3 = ex2(s[mi][nt][3] - mn1);
                l[mi][0] += p0 + p1;
                l[mi][1] += p2 + p3;
                unsigned long long u01 = (unsigned long long)f2tf(p0) |
                                         ((unsigned long long)f2tf(p1) << 32);
                unsigned long long u23 = (unsigned long long)f2tf(p2) |
                                         ((unsigned long long)f2tf(p3) << 32);
                *(unsigned long long*)&Ps[prow0][nt * 8 + 2 * tg]     = u01;
                *(unsigned long long*)&Ps[prow0 + 8][nt * 8 + 2 * tg] = u23;
            }
        }
        __syncwarp();

        // ---- O += P @ V ----
#pragma unroll
        for (int ks = 0; ks < 8; ks++) {
            unsigned b0[4], b1[4];
#pragma unroll
            for (int nt = 0; nt < 4; nt++) {
                b0[nt] = Vs[ks * 8 + tg][nt * 8 + g];
                b1[nt] = Vs[ks * 8 + tg + 4][nt * 8 + g];
            }
#pragma unroll
            for (int mi = 0; mi < 2; mi++) {
                const int prow = w * 32 + mi * 16 + g;
                unsigned a0 = Ps[prow][ks * 8 + tg];
                unsigned a1 = Ps[prow + 8][ks * 8 + tg];
                unsigned a2 = Ps[prow][ks * 8 + tg + 4];
                unsigned a3 = Ps[prow + 8][ks * 8 + tg + 4];
#pragma unroll
                for (int nt = 0; nt < 4; nt++)
                    mma_tf32(oacc[mi][nt], a0, a1, a2, a3, b0[nt], b1[nt]);
            }
        }

        if (kt + 1 < NT) {
            __syncthreads();
#pragma unroll
            for (int j = 0; j < 4; j++) {
                int idx = tid + j * 128;
                int key = idx >> 3, r4 = (idx & 7) * 4;
                *(uint4*)&Ks[key][r4] = kr[j];
                *(uint4*)&Vs[key][r4] = vr[j];
            }
            __syncthreads();
        }
    }

    // ---- finalize ----
    const int b = bh / H_;
    const int h = bh % H_;
#pragma unroll
    for (int mi = 0; mi < 2; mi++) {
        float l0 = l[mi][0], l1 = l[mi][1];
        l0 += __shfl_xor_sync(0xffffffff, l0, 1);
        l0 += __shfl_xor_sync(0xffffffff, l0, 2);
        l1 += __shfl_xor_sync(0xffffffff, l1, 1);
        l1 += __shfl_xor_sync(0xffffffff, l1, 2);
        const float inv0 = 1.0f / l0;
        const float inv1 = 1.0f / l1;

        const int row0 = qbase + w * 32 + mi * 16 + g;
        const int row1 = row0 + 8;
        float* o0 = o + (((size_t)b * N_ + row0) * H_ + h) * R_;
        float* o1 = o + (((size_t)b * N_ + row1) * H_ + h) * R_;
#pragma unroll
        for (int nt = 0; nt < 4; nt++) {
            int col = nt * 8 + 2 * tg;
            float2 f0 = { oacc[mi][nt][0] * inv0, oacc[mi][nt][1] * inv0 };
            float2 f1 = { oacc[mi][nt][2] * inv1, oacc[mi][nt][3] * inv1 };
            *(float2*)(o0 + col) = f0;
            *(float2*)(o1 + col) = f1;
        }
    }
}

// ---------------------------------------------------------------------------
extern "C" void kernel_launch(void* const* d_in, const int* in_sizes, int n_in,
                              void* d_out, int out_size)
{
    const float* x  = (const float*)d_in[0];
    const float* Wq = (const float*)d_in[1];
    const float* Wk = (const float*)d_in[2];
    const float* Wv = (const float*)d_in[3];
    const float* Wp = (const float*)d_in[4];
    float* out = (float*)d_out;

    unsigned *gq, *gk, *gv;
    float* go;
    cudaGetSymbolAddress((void**)&gq, g_q);
    cudaGetSymbolAddress((void**)&gk, g_k);
    cudaGetSymbolAddress((void**)&gv, g_v);
    cudaGetSymbolAddress((void**)&go, g_o);

    static bool attr_set = false;
    if (!attr_set) {
        cudaFuncSetAttribute(attn_tc_kernel,
                             cudaFuncAttributeMaxDynamicSharedMemorySize, SMEM_ATTN);
        attr_set = true;
    }

    // Fused QKV projections (tensor core, tf32-bit output, q pre-scaled)
    dim3 gProj(HR_ / 64, M_ / 128, 3);
    qkv_proj_kernel<<<gProj, 256>>>(x, Wq, Wk, Wv, gq, gk, gv);

    // attention (tensor core)
    dim3 gAttn(N_ / 128, B_ * H_);
    attn_tc_kernel<<<gAttn, 128, SMEM_ATTN>>>(gq, gk, gv, go);

    // output projection
    dim3 gOut(C_ / 64, M_ / 128);
    out_proj_kernel<<<gOut, 256>>>(go, Wp, out);
}

// round 8
// speedup vs baseline: 4.0233x; 1.0710x over previous
#include <cuda_runtime.h>

#define B_ 4
#define N_ 2048
#define C_ 768
#define H_ 12
#define R_ 32
#define M_ (B_ * N_)          // 8192 rows
#define HR_ (H_ * R_)         // 384

#define QSCALE (0.125f * 1.44269504f)   // head_dim^-0.5 * log2(e)

// Scratch (device globals; no allocations allowed)
// q/k/v/o hold tf32-bit patterns (q pre-scaled by QSCALE)
__device__ unsigned g_q[B_ * H_ * N_ * R_];
__device__ unsigned g_k[B_ * H_ * N_ * R_];
__device__ unsigned g_v[B_ * H_ * N_ * R_];
__device__ unsigned g_o[B_ * N_ * HR_];

// ---------------------------------------------------------------------------
// Common tf32 helpers
// ---------------------------------------------------------------------------
__device__ __forceinline__ unsigned f2tf(float f) {
    unsigned u; asm("cvt.rna.tf32.f32 %0, %1;" : "=r"(u) : "f"(f)); return u;
}
__device__ __forceinline__ float ex2(float x) {
    float r; asm("ex2.approx.ftz.f32 %0, %1;" : "=f"(r) : "f"(x)); return r;
}
__device__ __forceinline__ void mma_tf32(float* c, unsigned a0, unsigned a1,
                                         unsigned a2, unsigned a3,
                                         unsigned b0, unsigned b1) {
    asm("mma.sync.aligned.m16n8k8.row.col.f32.tf32.tf32.f32 "
        "{%0,%1,%2,%3},{%4,%5,%6,%7},{%8,%9},{%0,%1,%2,%3};"
        : "+f"(c[0]), "+f"(c[1]), "+f"(c[2]), "+f"(c[3])
        : "r"(a0), "r"(a1), "r"(a2), "r"(a3), "r"(b0), "r"(b1));
}

// ---------------------------------------------------------------------------
// TF32 tensor-core GEMM core. BM=128, BN=128, BK=32, 256 thr, 8 warps (2x4),
// warp tile 64x32 (4x4 m16n8 frags). LDS/MMA = 1.5.
// As[row][k] stride 36 (==4 mod 32): staging STS.128 + A-frag loads clean.
// Ws[k][n]  stride 136 (==8 mod 32): staging STS.128 + B-frag loads clean.
// MODE 0: float A -> float row-major C.
// MODE 1: float A -> scatter tf32-bits into [B,H,N,R] (scale folded).
// MODE 2: tf32-bit A (no cvt on staging) -> float row-major C.
// ---------------------------------------------------------------------------
#define AS_STRIDE 36
#define WS_STRIDE 136

template <int MODE>
__device__ __forceinline__ void gemm_tf32_body(
    const void* __restrict__ Av, const float* __restrict__ W,
    void* __restrict__ CoutV, int K, int Nc, int rowBase, int colBase,
    float oscale)
{
    __shared__ unsigned As[128][AS_STRIDE];   // [m][k]
    __shared__ unsigned Ws[32][WS_STRIDE];    // [k][n]

    const int tid  = threadIdx.x;
    const int w    = tid >> 5;
    const int lane = tid & 31;
    const int g    = lane >> 2;
    const int tg   = lane & 3;
    const int m0   = (w >> 2) * 64;    // 2 warp rows
    const int n0   = (w & 3) * 32;     // 4 warp cols

    const float*    Af = (const float*)Av;
    const unsigned* Au = (const unsigned*)Av;

    float acc[4][4][4] = {};
    float4 paf[4];
    uint4  pau[4];
    float4 pw[4];

    // ---- initial loads ----
#pragma unroll
    for (int j = 0; j < 4; j++) {
        int idx = tid + j * 256;
        if (MODE == 2)
            pau[j] = *(const uint4*)(Au + (size_t)(rowBase + (idx >> 3)) * K + (idx & 7) * 4);
        else
            paf[j] = *(const float4*)(Af + (size_t)(rowBase + (idx >> 3)) * K + (idx & 7) * 4);
    }
#pragma unroll
    for (int j = 0; j < 4; j++) {
        int idx = tid + j * 256;
        pw[j] = *(const float4*)(W + (size_t)(idx >> 5) * Nc + colBase + (idx & 31) * 4);
    }
#pragma unroll
    for (int j = 0; j < 4; j++) {
        int idx = tid + j * 256;
        int row = idx >> 3, k4 = (idx & 7) * 4;
        uint4 u;
        if (MODE == 2) u = pau[j];
        else { u.x = f2tf(paf[j].x); u.y = f2tf(paf[j].y); u.z = f2tf(paf[j].z); u.w = f2tf(paf[j].w); }
        *(uint4*)&As[row][k4] = u;
    }
#pragma unroll
    for (int j = 0; j < 4; j++) {
        int idx = tid + j * 256;
        int kr = idx >> 5, n4 = (idx & 31) * 4;
        uint4 u = { f2tf(pw[j].x), f2tf(pw[j].y), f2tf(pw[j].z), f2tf(pw[j].w) };
        *(uint4*)&Ws[kr][n4] = u;
    }
    __syncthreads();

    const int KT = K >> 5;
    for (int kt = 0; kt < KT; kt++) {
        if (kt + 1 < KT) {
            int kq = (kt + 1) * 32;
#pragma unroll
            for (int j = 0; j < 4; j++) {
                int idx = tid + j * 256;
                if (MODE == 2)
                    pau[j] = *(const uint4*)(Au + (size_t)(rowBase + (idx >> 3)) * K + kq + (idx & 7) * 4);
                else
                    paf[j] = *(const float4*)(Af + (size_t)(rowBase + (idx >> 3)) * K + kq + (idx & 7) * 4);
            }
#pragma unroll
            for (int j = 0; j < 4; j++) {
                int idx = tid + j * 256;
                pw[j] = *(const float4*)(W + (size_t)(kq + (idx >> 5)) * Nc + colBase + (idx & 31) * 4);
            }
        }

#pragma unroll
        for (int ks = 0; ks < 4; ks++) {
            const int kk = ks * 8;
            unsigned b0[4], b1[4];
#pragma unroll
            for (int ni = 0; ni < 4; ni++) {
                b0[ni] = Ws[kk + tg][n0 + ni * 8 + g];
                b1[ni] = Ws[kk + tg + 4][n0 + ni * 8 + g];
            }
#pragma unroll
            for (int mi = 0; mi < 4; mi++) {
                unsigned a0 = As[m0 + mi * 16 + g][kk + tg];
                unsigned a1 = As[m0 + mi * 16 + g + 8][kk + tg];
                unsigned a2 = As[m0 + mi * 16 + g][kk + tg + 4];
                unsigned a3 = As[m0 + mi * 16 + g + 8][kk + tg + 4];
#pragma unroll
                for (int ni = 0; ni < 4; ni++)
                    mma_tf32(acc[mi][ni], a0, a1, a2, a3, b0[ni], b1[ni]);
            }
        }

        if (kt + 1 < KT) {
            __syncthreads();
#pragma unroll
            for (int j = 0; j < 4; j++) {
                int idx = tid + j * 256;
                int row = idx >> 3, k4 = (idx & 7) * 4;
                uint4 u;
                if (MODE == 2) u = pau[j];
                else { u.x = f2tf(paf[j].x); u.y = f2tf(paf[j].y); u.z = f2tf(paf[j].z); u.w = f2tf(paf[j].w); }
                *(uint4*)&As[row][k4] = u;
            }
#pragma unroll
            for (int j = 0; j < 4; j++) {
                int idx = tid + j * 256;
                int kr = idx >> 5, n4 = (idx & 31) * 4;
                uint4 u = { f2tf(pw[j].x), f2tf(pw[j].y), f2tf(pw[j].z), f2tf(pw[j].w) };
                *(uint4*)&Ws[kr][n4] = u;
            }
            __syncthreads();
        }
    }

#pragma unroll
    for (int mi = 0; mi < 4; mi++) {
        int row0 = rowBase + m0 + mi * 16 + g;
        int row1 = row0 + 8;
#pragma unroll
        for (int ni = 0; ni < 4; ni++) {
            int col = colBase + n0 + ni * 8 + 2 * tg;
            if (MODE != 1) {
                float* Cout = (float*)CoutV;
                float2 f0 = { acc[mi][ni][0], acc[mi][ni][1] };
                float2 f1 = { acc[mi][ni][2], acc[mi][ni][3] };
                *(float2*)&Cout[(size_t)row0 * Nc + col] = f0;
                *(float2*)&Cout[(size_t)row1 * Nc + col] = f1;
            } else {
                unsigned* Cout = (unsigned*)CoutV;
                int h = col >> 5, rr = col & (R_ - 1);
                int b0r = row0 >> 11, n0r = row0 & (N_ - 1);
                int b1r = row1 >> 11, n1r = row1 & (N_ - 1);
                uint2 u0 = { f2tf(acc[mi][ni][0] * oscale), f2tf(acc[mi][ni][1] * oscale) };
                uint2 u1 = { f2tf(acc[mi][ni][2] * oscale), f2tf(acc[mi][ni][3] * oscale) };
                *(uint2*)&Cout[((((size_t)b0r * H_ + h) * N_) + n0r) * R_ + rr] = u0;
                *(uint2*)&Cout[((((size_t)b1r * H_ + h) * N_) + n1r) * R_ + rr] = u1;
            }
        }
    }
}

// Fused QKV projection: grid.z selects (q|k|v). Output = tf32 bits, q scaled.
__global__ __launch_bounds__(256) void qkv_proj_kernel(
    const float* __restrict__ x,
    const float* __restrict__ Wq, const float* __restrict__ Wk,
    const float* __restrict__ Wv,
    unsigned* __restrict__ oq, unsigned* __restrict__ ok,
    unsigned* __restrict__ ov)
{
    const int z = blockIdx.z;
    const float* W = (z == 0) ? Wq : (z == 1) ? Wk : Wv;
    unsigned* out  = (z == 0) ? oq : (z == 1) ? ok : ov;
    float scl      = (z == 0) ? QSCALE : 1.0f;
    gemm_tf32_body<1>(x, W, out, C_, HR_, blockIdx.y * 128, blockIdx.x * 128, scl);
}

// Final projection: tf32-bit A (attention output), float out, row-major.
__global__ __launch_bounds__(256) void out_proj_kernel(
    const unsigned* __restrict__ A, const float* __restrict__ W,
    float* __restrict__ Cout)
{
    gemm_tf32_body<2>(A, W, Cout, HR_, C_, blockIdx.y * 128, blockIdx.x * 128, 1.0f);
}

// ---------------------------------------------------------------------------
// Tensor-core flash attention (unchanged math; output stored as tf32 bits).
// ---------------------------------------------------------------------------
#define KS_STRIDE 36
#define VS_STRIDE 40
#define PS_STRIDE 68
#define SMEM_ATTN ((64 * KS_STRIDE + 64 * VS_STRIDE + 128 * PS_STRIDE) * 4)

__global__ __launch_bounds__(128) void attn_tc_kernel(
    const unsigned* __restrict__ q, const unsigned* __restrict__ k,
    const unsigned* __restrict__ v, unsigned* __restrict__ o)
{
    extern __shared__ unsigned smem[];
    unsigned (*Ks)[KS_STRIDE] = (unsigned(*)[KS_STRIDE])smem;
    unsigned (*Vs)[VS_STRIDE] = (unsigned(*)[VS_STRIDE])(smem + 64 * KS_STRIDE);
    unsigned (*Ps)[PS_STRIDE] = (unsigned(*)[PS_STRIDE])(smem + 64 * KS_STRIDE + 64 * VS_STRIDE);

    const int tid  = threadIdx.x;
    const int w    = tid >> 5;
    const int lane = tid & 31;
    const int g    = lane >> 2;
    const int tg   = lane & 3;
    const int bh   = blockIdx.y;
    const int qbase = blockIdx.x * 128;

    unsigned qa[2][4][4];
#pragma unroll
    for (int mi = 0; mi < 2; mi++) {
        const unsigned* q0 = q + ((size_t)bh * N_ + qbase + w * 32 + mi * 16 + g) * R_;
        const unsigned* q1 = q0 + 8 * R_;
#pragma unroll
        for (int ks = 0; ks < 4; ks++) {
            qa[mi][ks][0] = q0[ks * 8 + tg];
            qa[mi][ks][1] = q1[ks * 8 + tg];
            qa[mi][ks][2] = q0[ks * 8 + tg + 4];
            qa[mi][ks][3] = q1[ks * 8 + tg + 4];
        }
    }

    float m[2][2] = { {-1e30f, -1e30f}, {-1e30f, -1e30f} };
    float l[2][2] = {};
    float oacc[2][4][4] = {};

    const uint4* kg = (const uint4*)(k + (size_t)bh * N_ * R_);
    const uint4* vg = (const uint4*)(v + (size_t)bh * N_ * R_);

#pragma unroll
    for (int j = 0; j < 4; j++) {
        int idx = tid + j * 128;
        int key = idx >> 3, r4 = (idx & 7) * 4;
        *(uint4*)&Ks[key][r4] = kg[idx];
        *(uint4*)&Vs[key][r4] = vg[idx];
    }
    __syncthreads();

    const int NT = N_ / 64;
    for (int kt = 0; kt < NT; kt++) {
        uint4 kr[4], vr[4];
        if (kt + 1 < NT) {
            int base = (kt + 1) * 512;
#pragma unroll
            for (int j = 0; j < 4; j++) {
                kr[j] = kg[base + tid + j * 128];
                vr[j] = vg[base + tid + j * 128];
            }
        }

        float s[2][8][4];
#pragma unroll
        for (int mi = 0; mi < 2; mi++)
#pragma unroll
            for (int nt = 0; nt < 8; nt++) {
                s[mi][nt][0] = 0; s[mi][nt][1] = 0; s[mi][nt][2] = 0; s[mi][nt][3] = 0;
            }
#pragma unroll
        for (int nt = 0; nt < 8; nt++) {
#pragma unroll
            for (int ks = 0; ks < 4; ks++) {
                unsigned b0 = Ks[nt * 8 + g][ks * 8 + tg];
                unsigned b1 = Ks[nt * 8 + g][ks * 8 + tg + 4];
                mma_tf32(s[0][nt], qa[0][ks][0], qa[0][ks][1], qa[0][ks][2], qa[0][ks][3], b0, b1);
                mma_tf32(s[1][nt], qa[1][ks][0], qa[1][ks][1], qa[1][ks][2], qa[1][ks][3], b0, b1);
            }
        }

#pragma unroll
        for (int mi = 0; mi < 2; mi++) {
            float r0 = -1e30f, r1 = -1e30f;
#pragma unroll
            for (int nt = 0; nt < 8; nt++) {
                r0 = fmaxf(r0, fmaxf(s[mi][nt][0], s[mi][nt][1]));
                r1 = fmaxf(r1, fmaxf(s[mi][nt][2], s[mi][nt][3]));
            }
            r0 = fmaxf(r0, __shfl_xor_sync(0xffffffff, r0, 1));
            r0 = fmaxf(r0, __shfl_xor_sync(0xffffffff, r0, 2));
            r1 = fmaxf(r1, __shfl_xor_sync(0xffffffff, r1, 1));
            r1 = fmaxf(r1, __shfl_xor_sync(0xffffffff, r1, 2));

            float mn0 = fmaxf(m[mi][0], r0), mn1 = fmaxf(m[mi][1], r1);
            float al0 = ex2(m[mi][0] - mn0), al1 = ex2(m[mi][1] - mn1);
            m[mi][0] = mn0; m[mi][1] = mn1;
            l[mi][0] *= al0; l[mi][1] *= al1;
#pragma unroll
            for (int nt = 0; nt < 4; nt++) {
                oacc[mi][nt][0] *= al0; oacc[mi][nt][1] *= al0;
                oacc[mi][nt][2] *= al1; oacc[mi][nt][3] *= al1;
            }

            const int prow0 = w * 32 + mi * 16 + g;
#pragma unroll
            for (int nt = 0; nt < 8; nt++) {
                float p0 = ex2(s[mi][nt][0] - mn0);
                float p1 = ex2(s[mi][nt][1] - mn0);
                float p2 = ex2(s[mi][nt][2] - mn1);
                float p3 = ex2(s[mi][nt][3] - mn1);
                l[mi][0] += p0 + p1;
                l[mi][1] += p2 + p3;
                unsigned long long u01 = (unsigned long long)f2tf(p0) |
                                         ((unsigned long long)f2tf(p1) << 32);
                unsigned long long u23 = (unsigned long long)f2tf(p2) |
                                         ((unsigned long long)f2tf(p3) << 32);
                *(unsigned long long*)&Ps[prow0][nt * 8 + 2 * tg]     = u01;
                *(unsigned long long*)&Ps[prow0 + 8][nt * 8 + 2 * tg] = u23;
            }
        }
        __syncwarp();

#pragma unroll
        for (int ks = 0; ks < 8; ks++) {
            unsigned b0[4], b1[4];
#pragma unroll
            for (int nt = 0; nt < 4; nt++) {
                b0[nt] = Vs[ks * 8 + tg][nt * 8 + g];
                b1[nt] = Vs[ks * 8 + tg + 4][nt * 8 + g];
            }
#pragma unroll
            for (int mi = 0; mi < 2; mi++) {
                const int prow = w * 32 + mi * 16 + g;
                unsigned a0 = Ps[prow][ks * 8 + tg];
                unsigned a1 = Ps[prow + 8][ks * 8 + tg];
                unsigned a2 = Ps[prow][ks * 8 + tg + 4];
                unsigned a3 = Ps[prow + 8][ks * 8 + tg + 4];
#pragma unroll
                for (int nt = 0; nt < 4; nt++)
                    mma_tf32(oacc[mi][nt], a0, a1, a2, a3, b0[nt], b1[nt]);
            }
        }

        if (kt + 1 < NT) {
            __syncthreads();
#pragma unroll
            for (int j = 0; j < 4; j++) {
                int idx = tid + j * 128;
                int key = idx >> 3, r4 = (idx & 7) * 4;
                *(uint4*)&Ks[key][r4] = kr[j];
                *(uint4*)&Vs[key][r4] = vr[j];
            }
            __syncthreads();
        }
    }

    // ---- finalize: normalize, convert to tf32 bits for out_proj ----
    const int b = bh / H_;
    const int h = bh % H_;
#pragma unroll
    for (int mi = 0; mi < 2; mi++) {
        float l0 = l[mi][0], l1 = l[mi][1];
        l0 += __shfl_xor_sync(0xffffffff, l0, 1);
        l0 += __shfl_xor_sync(0xffffffff, l0, 2);
        l1 += __shfl_xor_sync(0xffffffff, l1, 1);
        l1 += __shfl_xor_sync(0xffffffff, l1, 2);
        const float inv0 = 1.0f / l0;
        const float inv1 = 1.0f / l1;

        const int row0 = qbase + w * 32 + mi * 16 + g;
        const int row1 = row0 + 8;
        unsigned* o0 = o + (((size_t)b * N_ + row0) * H_ + h) * R_;
        unsigned* o1 = o + (((size_t)b * N_ + row1) * H_ + h) * R_;
#pragma unroll
        for (int nt = 0; nt < 4; nt++) {
            int col = nt * 8 + 2 * tg;
            uint2 u0 = { f2tf(oacc[mi][nt][0] * inv0), f2tf(oacc[mi][nt][1] * inv0) };
            uint2 u1 = { f2tf(oacc[mi][nt][2] * inv1), f2tf(oacc[mi][nt][3] * inv1) };
            *(uint2*)(o0 + col) = u0;
            *(uint2*)(o1 + col) = u1;
        }
    }
}

// ---------------------------------------------------------------------------
extern "C" void kernel_launch(void* const* d_in, const int* in_sizes, int n_in,
                              void* d_out, int out_size)
{
    const float* x  = (const float*)d_in[0];
    const float* Wq = (const float*)d_in[1];
    const float* Wk = (const float*)d_in[2];
    const float* Wv = (const float*)d_in[3];
    const float* Wp = (const float*)d_in[4];
    float* out = (float*)d_out;

    unsigned *gq, *gk, *gv, *go;
    cudaGetSymbolAddress((void**)&gq, g_q);
    cudaGetSymbolAddress((void**)&gk, g_k);
    cudaGetSymbolAddress((void**)&gv, g_v);
    cudaGetSymbolAddress((void**)&go, g_o);

    static bool attr_set = false;
    if (!attr_set) {
        cudaFuncSetAttribute(attn_tc_kernel,
                             cudaFuncAttributeMaxDynamicSharedMemorySize, SMEM_ATTN);
        attr_set = true;
    }

    // Fused QKV projections (tensor core, tf32-bit output, q pre-scaled)
    dim3 gProj(HR_ / 128, M_ / 128, 3);
    qkv_proj_kernel<<<gProj, 256>>>(x, Wq, Wk, Wv, gq, gk, gv);

    // attention (tensor core)
    dim3 gAttn(N_ / 128, B_ * H_);
    attn_tc_kernel<<<gAttn, 128, SMEM_ATTN>>>(gq, gk, gv, go);

    // output projection (tf32-bit A input)
    dim3 gOut(C_ / 128, M_ / 128);
    out_proj_kernel<<<gOut, 256>>>(go, Wp, out);
}

// round 9
// speedup vs baseline: 5.3988x; 1.3419x over previous
#include <cuda_runtime.h>
#include <cuda_fp16.h>

#define B_ 4
#define N_ 2048
#define C_ 768
#define H_ 12
#define R_ 32
#define M_ (B_ * N_)          // 8192 rows
#define HR_ (H_ * R_)         // 384

#define QSCALE (0.125f * 1.44269504f)   // head_dim^-0.5 * log2(e)

// Scratch (device globals; no allocations allowed)
__device__ __half   g_xh[M_ * C_];          // x in half
__device__ __half   g_wqt[HR_ * C_];        // Wq^T [384][768] half
__device__ __half   g_wkt[HR_ * C_];
__device__ __half   g_wvt[HR_ * C_];
__device__ __half   g_wpt[C_ * HR_];        // Wp^T [768][384] half
__device__ __half   g_qh[B_ * H_ * N_ * R_];   // q half, pre-scaled
__device__ __half   g_kh[B_ * H_ * N_ * R_];   // k half
__device__ unsigned g_v [B_ * H_ * N_ * R_];   // v tf32 bits
__device__ __half   g_oh[B_ * N_ * HR_];       // attention out, half

// ---------------------------------------------------------------------------
// helpers
// ---------------------------------------------------------------------------
__device__ __forceinline__ unsigned f2tf(float f) {
    unsigned u; asm("cvt.rna.tf32.f32 %0, %1;" : "=r"(u) : "f"(f)); return u;
}
__device__ __forceinline__ float ex2(float x) {
    float r; asm("ex2.approx.ftz.f32 %0, %1;" : "=f"(r) : "f"(x)); return r;
}
__device__ __forceinline__ unsigned packh2(float lo, float hi) {
    __half2 h = __floats2half2_rn(lo, hi);
    return *(unsigned*)&h;
}
__device__ __forceinline__ void mma_tf32(float* c, unsigned a0, unsigned a1,
                                         unsigned a2, unsigned a3,
                                         unsigned b0, unsigned b1) {
    asm("mma.sync.aligned.m16n8k8.row.col.f32.tf32.tf32.f32 "
        "{%0,%1,%2,%3},{%4,%5,%6,%7},{%8,%9},{%0,%1,%2,%3};"
        : "+f"(c[0]), "+f"(c[1]), "+f"(c[2]), "+f"(c[3])
        : "r"(a0), "r"(a1), "r"(a2), "r"(a3), "r"(b0), "r"(b1));
}
__device__ __forceinline__ void mma_f16(float* c, unsigned a0, unsigned a1,
                                        unsigned a2, unsigned a3,
                                        unsigned b0, unsigned b1) {
    asm("mma.sync.aligned.m16n8k16.row.col.f32.f16.f16.f32 "
        "{%0,%1,%2,%3},{%4,%5,%6,%7},{%8,%9},{%0,%1,%2,%3};"
        : "+f"(c[0]), "+f"(c[1]), "+f"(c[2]), "+f"(c[3])
        : "r"(a0), "r"(a1), "r"(a2), "r"(a3), "r"(b0), "r"(b1));
}

// ---------------------------------------------------------------------------
// Prep: x -> half
// ---------------------------------------------------------------------------
__global__ __launch_bounds__(256) void x_to_half_kernel(
    const float* __restrict__ x, __half* __restrict__ xh)
{
    int i = (blockIdx.x * 256 + threadIdx.x) * 8;
    float4 f0 = *(const float4*)(x + i);
    float4 f1 = *(const float4*)(x + i + 4);
    __half2 h0 = __floats2half2_rn(f0.x, f0.y);
    __half2 h1 = __floats2half2_rn(f0.z, f0.w);
    __half2 h2 = __floats2half2_rn(f1.x, f1.y);
    __half2 h3 = __floats2half2_rn(f1.z, f1.w);
    uint4 u = { *(unsigned*)&h0, *(unsigned*)&h1, *(unsigned*)&h2, *(unsigned*)&h3 };
    *(uint4*)(xh + i) = u;
}

// ---------------------------------------------------------------------------
// Prep: transpose W [K][N] float -> Wt [N][K] half. grid.z selects matrix.
// ---------------------------------------------------------------------------
__global__ __launch_bounds__(256) void w_transpose_kernel(
    const float* __restrict__ Wq, const float* __restrict__ Wk,
    const float* __restrict__ Wv, const float* __restrict__ Wp,
    __half* __restrict__ wqt, __half* __restrict__ wkt,
    __half* __restrict__ wvt, __half* __restrict__ wpt)
{
    __shared__ float t[32][33];
    const int z = blockIdx.z;
    const float* W = (z == 0) ? Wq : (z == 1) ? Wk : (z == 2) ? Wv : Wp;
    __half* Wt     = (z == 0) ? wqt : (z == 1) ? wkt : (z == 2) ? wvt : wpt;
    const int Kd = (z < 3) ? C_ : HR_;
    const int Nd = (z < 3) ? HR_ : C_;

    const int bx = blockIdx.x, by = blockIdx.y;
    if (bx * 32 >= Nd || by * 32 >= Kd) return;
    const int tx = threadIdx.x & 31;
    const int ty = threadIdx.x >> 5;   // 0..7

#pragma unroll
    for (int i = 0; i < 4; i++)
        t[ty + i * 8][tx] = W[(size_t)(by * 32 + ty + i * 8) * Nd + bx * 32 + tx];
    __syncthreads();
#pragma unroll
    for (int i = 0; i < 4; i++)
        Wt[(size_t)(bx * 32 + ty + i * 8) * Kd + by * 32 + tx] =
            __float2half_rn(t[tx][ty + i * 8]);
}

// ---------------------------------------------------------------------------
// FP16 tensor-core GEMM. BM=128, BN=128, BK=32, 256 thr, 8 warps (2x4),
// warp tile 64x32 (4x4 m16n8 frags), m16n8k16.
// A [M][K] half row-major; Wt [N][K] half row-major (pre-transposed).
// Smem rows: 32 halves = 16 words, padded stride 20 (bank = 20g+tg distinct).
// OUT 0: float C row-major. OUT 1: half scatter [B,H,N,R] (scale folded).
// OUT 2: tf32-bit scatter [B,H,N,R].
// ---------------------------------------------------------------------------
#define GS_STRIDE 20

template <int OUT>
__device__ __forceinline__ void gemm_f16_body(
    const __half* __restrict__ A, const __half* __restrict__ Wt,
    void* __restrict__ Cv, int K, int Nc, int rowBase, int colBase,
    float oscale)
{
    __shared__ unsigned As[128][GS_STRIDE];   // [m][word]
    __shared__ unsigned Ws[128][GS_STRIDE];   // [n][word]

    const int tid  = threadIdx.x;
    const int w    = tid >> 5;
    const int lane = tid & 31;
    const int g    = lane >> 2;
    const int tg   = lane & 3;
    const int m0   = (w >> 2) * 64;
    const int n0   = (w & 3) * 32;

    float acc[4][4][4] = {};
    uint4 pa[2], pw[2];

#pragma unroll
    for (int j = 0; j < 2; j++) {
        int idx = tid + j * 256;
        int row = idx >> 2, c4 = idx & 3;
        pa[j] = *(const uint4*)(A  + (size_t)(rowBase + row) * K + c4 * 8);
        pw[j] = *(const uint4*)(Wt + (size_t)(colBase + row) * K + c4 * 8);
    }
#pragma unroll
    for (int j = 0; j < 2; j++) {
        int idx = tid + j * 256;
        int row = idx >> 2, c4 = idx & 3;
        *(uint4*)&As[row][c4 * 4] = pa[j];
        *(uint4*)&Ws[row][c4 * 4] = pw[j];
    }
    __syncthreads();

    const int KT = K >> 5;
    for (int kt = 0; kt < KT; kt++) {
        if (kt + 1 < KT) {
            int kq = (kt + 1) * 32;
#pragma unroll
            for (int j = 0; j < 2; j++) {
                int idx = tid + j * 256;
                int row = idx >> 2, c4 = idx & 3;
                pa[j] = *(const uint4*)(A  + (size_t)(rowBase + row) * K + kq + c4 * 8);
                pw[j] = *(const uint4*)(Wt + (size_t)(colBase + row) * K + kq + c4 * 8);
            }
        }

#pragma unroll
        for (int c = 0; c < 2; c++) {
            unsigned b0[4], b1[4];
#pragma unroll
            for (int ni = 0; ni < 4; ni++) {
                int n = n0 + ni * 8 + g;
                b0[ni] = Ws[n][c * 8 + tg];
                b1[ni] = Ws[n][c * 8 + tg + 4];
            }
#pragma unroll
            for (int mi = 0; mi < 4; mi++) {
                int mr = m0 + mi * 16 + g;
                unsigned a0 = As[mr][c * 8 + tg];
                unsigned a1 = As[mr + 8][c * 8 + tg];
                unsigned a2 = As[mr][c * 8 + tg + 4];
                unsigned a3 = As[mr + 8][c * 8 + tg + 4];
#pragma unroll
                for (int ni = 0; ni < 4; ni++)
                    mma_f16(acc[mi][ni], a0, a1, a2, a3, b0[ni], b1[ni]);
            }
        }

        if (kt + 1 < KT) {
            __syncthreads();
#pragma unroll
            for (int j = 0; j < 2; j++) {
                int idx = tid + j * 256;
                int row = idx >> 2, c4 = idx & 3;
                *(uint4*)&As[row][c4 * 4] = pa[j];
                *(uint4*)&Ws[row][c4 * 4] = pw[j];
            }
            __syncthreads();
        }
    }

#pragma unroll
    for (int mi = 0; mi < 4; mi++) {
        int row0 = rowBase + m0 + mi * 16 + g;
        int row1 = row0 + 8;
#pragma unroll
        for (int ni = 0; ni < 4; ni++) {
            int col = colBase + n0 + ni * 8 + 2 * tg;
            if (OUT == 0) {
                float* Cout = (float*)Cv;
                float2 f0 = { acc[mi][ni][0], acc[mi][ni][1] };
                float2 f1 = { acc[mi][ni][2], acc[mi][ni][3] };
                *(float2*)&Cout[(size_t)row0 * Nc + col] = f0;
                *(float2*)&Cout[(size_t)row1 * Nc + col] = f1;
            } else {
                int h = col >> 5, rr = col & (R_ - 1);
                int b0r = row0 >> 11, n0r = row0 & (N_ - 1);
                int b1r = row1 >> 11, n1r = row1 & (N_ - 1);
                size_t i0 = ((((size_t)b0r * H_ + h) * N_) + n0r) * R_ + rr;
                size_t i1 = ((((size_t)b1r * H_ + h) * N_) + n1r) * R_ + rr;
                if (OUT == 1) {
                    __half* Ch = (__half*)Cv;
                    *(unsigned*)(Ch + i0) = packh2(acc[mi][ni][0] * oscale, acc[mi][ni][1] * oscale);
                    *(unsigned*)(Ch + i1) = packh2(acc[mi][ni][2] * oscale, acc[mi][ni][3] * oscale);
                } else {
                    unsigned* Cu = (unsigned*)Cv;
                    uint2 u0 = { f2tf(acc[mi][ni][0]), f2tf(acc[mi][ni][1]) };
                    uint2 u1 = { f2tf(acc[mi][ni][2]), f2tf(acc[mi][ni][3]) };
                    *(uint2*)(Cu + i0) = u0;
                    *(uint2*)(Cu + i1) = u1;
                }
            }
        }
    }
}

__global__ __launch_bounds__(256) void qkv_proj_kernel(
    const __half* __restrict__ xh,
    const __half* __restrict__ wqt, const __half* __restrict__ wkt,
    const __half* __restrict__ wvt,
    __half* __restrict__ oq, __half* __restrict__ ok,
    unsigned* __restrict__ ov)
{
    const int z = blockIdx.z;
    const int rb = blockIdx.y * 128, cb = blockIdx.x * 128;
    if (z == 0)      gemm_f16_body<1>(xh, wqt, oq, C_, HR_, rb, cb, QSCALE);
    else if (z == 1) gemm_f16_body<1>(xh, wkt, ok, C_, HR_, rb, cb, 1.0f);
    else             gemm_f16_body<2>(xh, wvt, ov, C_, HR_, rb, cb, 1.0f);
}

__global__ __launch_bounds__(256) void out_proj_kernel(
    const __half* __restrict__ A, const __half* __restrict__ wpt,
    float* __restrict__ Cout)
{
    gemm_f16_body<0>(A, wpt, Cout, HR_, C_, blockIdx.y * 128, blockIdx.x * 128, 1.0f);
}

// ---------------------------------------------------------------------------
// Flash attention: QK^T in fp16 m16n8k16, P@V in tf32 m16n8k8.
// Ks[key][r] half (stride 20 words), Vs[key][r] tf32 (stride 40),
// Ps[qrow][key] tf32 (stride 68). 128 thr, q-block 128.
// ---------------------------------------------------------------------------
#define KS_STRIDE 20
#define VS_STRIDE 40
#define PS_STRIDE 68
#define SMEM_ATTN ((64 * KS_STRIDE + 64 * VS_STRIDE + 128 * PS_STRIDE) * 4)

__global__ __launch_bounds__(128) void attn_tc_kernel(
    const __half* __restrict__ q, const __half* __restrict__ k,
    const unsigned* __restrict__ v, __half* __restrict__ o)
{
    extern __shared__ unsigned smem[];
    unsigned (*Ks)[KS_STRIDE] = (unsigned(*)[KS_STRIDE])smem;
    unsigned (*Vs)[VS_STRIDE] = (unsigned(*)[VS_STRIDE])(smem + 64 * KS_STRIDE);
    unsigned (*Ps)[PS_STRIDE] = (unsigned(*)[PS_STRIDE])(smem + 64 * KS_STRIDE + 64 * VS_STRIDE);

    const int tid  = threadIdx.x;
    const int w    = tid >> 5;
    const int lane = tid & 31;
    const int g    = lane >> 2;
    const int tg   = lane & 3;
    const int bh   = blockIdx.y;
    const int qbase = blockIdx.x * 128;

    // Q fragments: half pairs. qa[mi][c][4]
    unsigned qa[2][2][4];
#pragma unroll
    for (int mi = 0; mi < 2; mi++) {
        const __half* q0 = q + ((size_t)bh * N_ + qbase + w * 32 + mi * 16 + g) * R_;
        const __half* q1 = q0 + 8 * R_;
#pragma unroll
        for (int c = 0; c < 2; c++) {
            qa[mi][c][0] = *(const unsigned*)(q0 + c * 16 + 2 * tg);
            qa[mi][c][1] = *(const unsigned*)(q1 + c * 16 + 2 * tg);
            qa[mi][c][2] = *(const unsigned*)(q0 + c * 16 + 2 * tg + 8);
            qa[mi][c][3] = *(const unsigned*)(q1 + c * 16 + 2 * tg + 8);
        }
    }

    float m[2][2] = { {-1e30f, -1e30f}, {-1e30f, -1e30f} };
    float l[2][2] = {};
    float oacc[2][4][4] = {};

    const uint4* kg = (const uint4*)(k + (size_t)bh * N_ * R_);   // 8 halves each
    const uint4* vg = (const uint4*)(v + (size_t)bh * N_ * R_);   // 4 words each

    // preload tile 0
#pragma unroll
    for (int j = 0; j < 2; j++) {           // K: 256 uint4/tile
        int idx = tid + j * 128;
        int key = idx >> 2, c4 = idx & 3;
        *(uint4*)&Ks[key][c4 * 4] = kg[idx];
    }
#pragma unroll
    for (int j = 0; j < 4; j++) {           // V: 512 uint4/tile
        int idx = tid + j * 128;
        int key = idx >> 3, r4 = (idx & 7) * 4;
        *(uint4*)&Vs[key][r4] = vg[idx];
    }
    __syncthreads();

    const int NT = N_ / 64;
    for (int kt = 0; kt < NT; kt++) {
        uint4 kr[2], vr[4];
        if (kt + 1 < NT) {
            int kbase = (kt + 1) * 256;
            int vbase = (kt + 1) * 512;
#pragma unroll
            for (int j = 0; j < 2; j++) kr[j] = kg[kbase + tid + j * 128];
#pragma unroll
            for (int j = 0; j < 4; j++) vr[j] = vg[vbase + tid + j * 128];
        }

        // ---- S = Q @ K^T (fp16 k16) ----
        float s[2][8][4];
#pragma unroll
        for (int mi = 0; mi < 2; mi++)
#pragma unroll
            for (int nt = 0; nt < 8; nt++) {
                s[mi][nt][0] = 0; s[mi][nt][1] = 0; s[mi][nt][2] = 0; s[mi][nt][3] = 0;
            }
#pragma unroll
        for (int nt = 0; nt < 8; nt++) {
#pragma unroll
            for (int c = 0; c < 2; c++) {
                unsigned b0 = Ks[nt * 8 + g][c * 8 + tg];
                unsigned b1 = Ks[nt * 8 + g][c * 8 + tg + 4];
                mma_f16(s[0][nt], qa[0][c][0], qa[0][c][1], qa[0][c][2], qa[0][c][3], b0, b1);
                mma_f16(s[1][nt], qa[1][c][0], qa[1][c][1], qa[1][c][2], qa[1][c][3], b0, b1);
            }
        }

        // ---- online softmax + P store (tf32) ----
#pragma unroll
        for (int mi = 0; mi < 2; mi++) {
            float r0 = -1e30f, r1 = -1e30f;
#pragma unroll
            for (int nt = 0; nt < 8; nt++) {
                r0 = fmaxf(r0, fmaxf(s[mi][nt][0], s[mi][nt][1]));
                r1 = fmaxf(r1, fmaxf(s[mi][nt][2], s[mi][nt][3]));
            }
            r0 = fmaxf(r0, __shfl_xor_sync(0xffffffff, r0, 1));
            r0 = fmaxf(r0, __shfl_xor_sync(0xffffffff, r0, 2));
            r1 = fmaxf(r1, __shfl_xor_sync(0xffffffff, r1, 1));
            r1 = fmaxf(r1, __shfl_xor_sync(0xffffffff, r1, 2));

            float mn0 = fmaxf(m[mi][0], r0), mn1 = fmaxf(m[mi][1], r1);
            float al0 = ex2(m[mi][0] - mn0), al1 = ex2(m[mi][1] - mn1);
            m[mi][0] = mn0; m[mi][1] = mn1;
            l[mi][0] *= al0; l[mi][1] *= al1;
#pragma unroll
            for (int nt = 0; nt < 4; nt++) {
                oacc[mi][nt][0] *= al0; oacc[mi][nt][1] *= al0;
                oacc[mi][nt][2] *= al1; oacc[mi][nt][3] *= al1;
            }

            const int prow0 = w * 32 + mi * 16 + g;
#pragma unroll
            for (int nt = 0; nt < 8; nt++) {
                float p0 = ex2(s[mi][nt][0] - mn0);
                float p1 = ex2(s[mi][nt][1] - mn0);
                float p2 = ex2(s[mi][nt][2] - mn1);
                float p3 = ex2(s[mi][nt][3] - mn1);
                l[mi][0] += p0 + p1;
                l[mi][1] += p2 + p3;
                unsigned long long u01 = (unsigned long long)f2tf(p0) |
                                         ((unsigned long long)f2tf(p1) << 32);
                unsigned long long u23 = (unsigned long long)f2tf(p2) |
                                         ((unsigned long long)f2tf(p3) << 32);
                *(unsigned long long*)&Ps[prow0][nt * 8 + 2 * tg]     = u01;
                *(unsigned long long*)&Ps[prow0 + 8][nt * 8 + 2 * tg] = u23;
            }
        }
        __syncwarp();

        // ---- O += P @ V (tf32 k8) ----
#pragma unroll
        for (int ks = 0; ks < 8; ks++) {
            unsigned b0[4], b1[4];
#pragma unroll
            for (int nt = 0; nt < 4; nt++) {
                b0[nt] = Vs[ks * 8 + tg][nt * 8 + g];
                b1[nt] = Vs[ks * 8 + tg + 4][nt * 8 + g];
            }
#pragma unroll
            for (int mi = 0; mi < 2; mi++) {
                const int prow = w * 32 + mi * 16 + g;
                unsigned a0 = Ps[prow][ks * 8 + tg];
                unsigned a1 = Ps[prow + 8][ks * 8 + tg];
                unsigned a2 = Ps[prow][ks * 8 + tg + 4];
                unsigned a3 = Ps[prow + 8][ks * 8 + tg + 4];
#pragma unroll
                for (int nt = 0; nt < 4; nt++)
                    mma_tf32(oacc[mi][nt], a0, a1, a2, a3, b0[nt], b1[nt]);
            }
        }

        if (kt + 1 < NT) {
            __syncthreads();
#pragma unroll
            for (int j = 0; j < 2; j++) {
                int idx = tid + j * 128;
                int key = idx >> 2, c4 = idx & 3;
                *(uint4*)&Ks[key][c4 * 4] = kr[j];
            }
#pragma unroll
            for (int j = 0; j < 4; j++) {
                int idx = tid + j * 128;
                int key = idx >> 3, r4 = (idx & 7) * 4;
                *(uint4*)&Vs[key][r4] = vr[j];
            }
            __syncthreads();
        }
    }

    // ---- finalize: normalize, store half ----
    const int b = bh / H_;
    const int h = bh % H_;
#pragma unroll
    for (int mi = 0; mi < 2; mi++) {
        float l0 = l[mi][0], l1 = l[mi][1];
        l0 += __shfl_xor_sync(0xffffffff, l0, 1);
        l0 += __shfl_xor_sync(0xffffffff, l0, 2);
        l1 += __shfl_xor_sync(0xffffffff, l1, 1);
        l1 += __shfl_xor_sync(0xffffffff, l1, 2);
        const float inv0 = 1.0f / l0;
        const float inv1 = 1.0f / l1;

        const int row0 = qbase + w * 32 + mi * 16 + g;
        const int row1 = row0 + 8;
        __half* o0 = o + (((size_t)b * N_ + row0) * H_ + h) * R_;
        __half* o1 = o + (((size_t)b * N_ + row1) * H_ + h) * R_;
#pragma unroll
        for (int nt = 0; nt < 4; nt++) {
            int col = nt * 8 + 2 * tg;
            *(unsigned*)(o0 + col) = packh2(oacc[mi][nt][0] * inv0, oacc[mi][nt][1] * inv0);
            *(unsigned*)(o1 + col) = packh2(oacc[mi][nt][2] * inv1, oacc[mi][nt][3] * inv1);
        }
    }
}

// ---------------------------------------------------------------------------
extern "C" void kernel_launch(void* const* d_in, const int* in_sizes, int n_in,
                              void* d_out, int out_size)
{
    const float* x  = (const float*)d_in[0];
    const float* Wq = (const float*)d_in[1];
    const float* Wk = (const float*)d_in[2];
    const float* Wv = (const float*)d_in[3];
    const float* Wp = (const float*)d_in[4];
    float* out = (float*)d_out;

    __half *xh, *wqt, *wkt, *wvt, *wpt, *qh, *kh, *oh;
    unsigned* vv;
    cudaGetSymbolAddress((void**)&xh,  g_xh);
    cudaGetSymbolAddress((void**)&wqt, g_wqt);
    cudaGetSymbolAddress((void**)&wkt, g_wkt);
    cudaGetSymbolAddress((void**)&wvt, g_wvt);
    cudaGetSymbolAddress((void**)&wpt, g_wpt);
    cudaGetSymbolAddress((void**)&qh,  g_qh);
    cudaGetSymbolAddress((void**)&kh,  g_kh);
    cudaGetSymbolAddress((void**)&vv,  g_v);
    cudaGetSymbolAddress((void**)&oh,  g_oh);

    static bool attr_set = false;
    if (!attr_set) {
        cudaFuncSetAttribute(attn_tc_kernel,
                             cudaFuncAttributeMaxDynamicSharedMemorySize, SMEM_ATTN);
        attr_set = true;
    }

    // prep: x->half, W transposes->half
    x_to_half_kernel<<<M_ * C_ / 2048, 256>>>(x, xh);
    dim3 gT(C_ / 32, C_ / 32, 4);
    w_transpose_kernel<<<gT, 256>>>(Wq, Wk, Wv, Wp, wqt, wkt, wvt, wpt);

    // QKV projections (fp16 tensor core)
    dim3 gProj(HR_ / 128, M_ / 128, 3);
    qkv_proj_kernel<<<gProj, 256>>>(xh, wqt, wkt, wvt, qh, kh, vv);

    // attention
    dim3 gAttn(N_ / 128, B_ * H_);
    attn_tc_kernel<<<gAttn, 128, SMEM_ATTN>>>(qh, kh, vv, oh);

    // output projection
    dim3 gOut(C_ / 128, M_ / 128);
    out_proj_kernel<<<gOut, 256>>>(oh, wpt, out);
}

// round 10
// speedup vs baseline: 6.5710x; 1.2171x over previous
#include <cuda_runtime.h>
#include <cuda_fp16.h>

#define B_ 4
#define N_ 2048
#define C_ 768
#define H_ 12
#define R_ 32
#define M_ (B_ * N_)          // 8192 rows
#define HR_ (H_ * R_)         // 384

#define QSCALE (0.125f * 1.44269504f)   // head_dim^-0.5 * log2(e)

// Scratch (device globals; no allocations allowed)
__device__ __half   g_xh[M_ * C_];          // x in half
__device__ __half   g_wqt[HR_ * C_];        // Wq^T [384][768] half
__device__ __half   g_wkt[HR_ * C_];
__device__ __half   g_wvt[HR_ * C_];
__device__ __half   g_wpt[C_ * HR_];        // Wp^T [768][384] half
__device__ __half   g_qh[B_ * H_ * N_ * R_];   // q half, pre-scaled
__device__ __half   g_kh[B_ * H_ * N_ * R_];   // k half
__device__ __half   g_vt[B_ * H_ * R_ * N_];   // v half, TRANSPOSED [B,H,R,N]
__device__ __half   g_oh[B_ * N_ * HR_];       // attention out, half

// ---------------------------------------------------------------------------
// helpers
// ---------------------------------------------------------------------------
__device__ __forceinline__ float ex2(float x) {
    float r; asm("ex2.approx.ftz.f32 %0, %1;" : "=f"(r) : "f"(x)); return r;
}
__device__ __forceinline__ unsigned packh2(float lo, float hi) {
    __half2 h = __floats2half2_rn(lo, hi);
    return *(unsigned*)&h;
}
__device__ __forceinline__ void mma_f16(float* c, unsigned a0, unsigned a1,
                                        unsigned a2, unsigned a3,
                                        unsigned b0, unsigned b1) {
    asm("mma.sync.aligned.m16n8k16.row.col.f32.f16.f16.f32 "
        "{%0,%1,%2,%3},{%4,%5,%6,%7},{%8,%9},{%0,%1,%2,%3};"
        : "+f"(c[0]), "+f"(c[1]), "+f"(c[2]), "+f"(c[3])
        : "r"(a0), "r"(a1), "r"(a2), "r"(a3), "r"(b0), "r"(b1));
}

// ---------------------------------------------------------------------------
// Prep: x -> half
// ---------------------------------------------------------------------------
__global__ __launch_bounds__(256) void x_to_half_kernel(
    const float* __restrict__ x, __half* __restrict__ xh)
{
    int i = (blockIdx.x * 256 + threadIdx.x) * 8;
    float4 f0 = *(const float4*)(x + i);
    float4 f1 = *(const float4*)(x + i + 4);
    __half2 h0 = __floats2half2_rn(f0.x, f0.y);
    __half2 h1 = __floats2half2_rn(f0.z, f0.w);
    __half2 h2 = __floats2half2_rn(f1.x, f1.y);
    __half2 h3 = __floats2half2_rn(f1.z, f1.w);
    uint4 u = { *(unsigned*)&h0, *(unsigned*)&h1, *(unsigned*)&h2, *(unsigned*)&h3 };
    *(uint4*)(xh + i) = u;
}

// ---------------------------------------------------------------------------
// Prep: transpose W [K][N] float -> Wt [N][K] half. grid.z selects matrix.
// ---------------------------------------------------------------------------
__global__ __launch_bounds__(256) void w_transpose_kernel(
    const float* __restrict__ Wq, const float* __restrict__ Wk,
    const float* __restrict__ Wv, const float* __restrict__ Wp,
    __half* __restrict__ wqt, __half* __restrict__ wkt,
    __half* __restrict__ wvt, __half* __restrict__ wpt)
{
    __shared__ float t[32][33];
    const int z = blockIdx.z;
    const float* W = (z == 0) ? Wq : (z == 1) ? Wk : (z == 2) ? Wv : Wp;
    __half* Wt     = (z == 0) ? wqt : (z == 1) ? wkt : (z == 2) ? wvt : wpt;
    const int Kd = (z < 3) ? C_ : HR_;
    const int Nd = (z < 3) ? HR_ : C_;

    const int bx = blockIdx.x, by = blockIdx.y;
    if (bx * 32 >= Nd || by * 32 >= Kd) return;
    const int tx = threadIdx.x & 31;
    const int ty = threadIdx.x >> 5;   // 0..7

#pragma unroll
    for (int i = 0; i < 4; i++)
        t[ty + i * 8][tx] = W[(size_t)(by * 32 + ty + i * 8) * Nd + bx * 32 + tx];
    __syncthreads();
#pragma unroll
    for (int i = 0; i < 4; i++)
        Wt[(size_t)(bx * 32 + ty + i * 8) * Kd + by * 32 + tx] =
            __float2half_rn(t[tx][ty + i * 8]);
}

// ---------------------------------------------------------------------------
// FP16 tensor-core GEMM. BM=128, BN=128, BK=32, 256 thr, 8 warps (2x4),
// warp tile 64x32 (4x4 m16n8 frags), m16n8k16.
// OUT 0: float C row-major. OUT 1: half scatter [B,H,N,R] (scale folded).
// OUT 3: half scatter TRANSPOSED [B,H,R,N] (for V).
// ---------------------------------------------------------------------------
#define GS_STRIDE 20

template <int OUT>
__device__ __forceinline__ void gemm_f16_body(
    const __half* __restrict__ A, const __half* __restrict__ Wt,
    void* __restrict__ Cv, int K, int Nc, int rowBase, int colBase,
    float oscale)
{
    __shared__ unsigned As[128][GS_STRIDE];   // [m][word]
    __shared__ unsigned Ws[128][GS_STRIDE];   // [n][word]

    const int tid  = threadIdx.x;
    const int w    = tid >> 5;
    const int lane = tid & 31;
    const int g    = lane >> 2;
    const int tg   = lane & 3;
    const int m0   = (w >> 2) * 64;
    const int n0   = (w & 3) * 32;

    float acc[4][4][4] = {};
    uint4 pa[2], pw[2];

#pragma unroll
    for (int j = 0; j < 2; j++) {
        int idx = tid + j * 256;
        int row = idx >> 2, c4 = idx & 3;
        pa[j] = *(const uint4*)(A  + (size_t)(rowBase + row) * K + c4 * 8);
        pw[j] = *(const uint4*)(Wt + (size_t)(colBase + row) * K + c4 * 8);
    }
#pragma unroll
    for (int j = 0; j < 2; j++) {
        int idx = tid + j * 256;
        int row = idx >> 2, c4 = idx & 3;
        *(uint4*)&As[row][c4 * 4] = pa[j];
        *(uint4*)&Ws[row][c4 * 4] = pw[j];
    }
    __syncthreads();

    const int KT = K >> 5;
    for (int kt = 0; kt < KT; kt++) {
        if (kt + 1 < KT) {
            int kq = (kt + 1) * 32;
#pragma unroll
            for (int j = 0; j < 2; j++) {
                int idx = tid + j * 256;
                int row = idx >> 2, c4 = idx & 3;
                pa[j] = *(const uint4*)(A  + (size_t)(rowBase + row) * K + kq + c4 * 8);
                pw[j] = *(const uint4*)(Wt + (size_t)(colBase + row) * K + kq + c4 * 8);
            }
        }

#pragma unroll
        for (int c = 0; c < 2; c++) {
            unsigned b0[4], b1[4];
#pragma unroll
            for (int ni = 0; ni < 4; ni++) {
                int n = n0 + ni * 8 + g;
                b0[ni] = Ws[n][c * 8 + tg];
                b1[ni] = Ws[n][c * 8 + tg + 4];
            }
#pragma unroll
            for (int mi = 0; mi < 4; mi++) {
                int mr = m0 + mi * 16 + g;
                unsigned a0 = As[mr][c * 8 + tg];
                unsigned a1 = As[mr + 8][c * 8 + tg];
                unsigned a2 = As[mr][c * 8 + tg + 4];
                unsigned a3 = As[mr + 8][c * 8 + tg + 4];
#pragma unroll
                for (int ni = 0; ni < 4; ni++)
                    mma_f16(acc[mi][ni], a0, a1, a2, a3, b0[ni], b1[ni]);
            }
        }

        if (kt + 1 < KT) {
            __syncthreads();
#pragma unroll
            for (int j = 0; j < 2; j++) {
                int idx = tid + j * 256;
                int row = idx >> 2, c4 = idx & 3;
                *(uint4*)&As[row][c4 * 4] = pa[j];
                *(uint4*)&Ws[row][c4 * 4] = pw[j];
            }
            __syncthreads();
        }
    }

#pragma unroll
    for (int mi = 0; mi < 4; mi++) {
        int row0 = rowBase + m0 + mi * 16 + g;
        int row1 = row0 + 8;
#pragma unroll
        for (int ni = 0; ni < 4; ni++) {
            int col = colBase + n0 + ni * 8 + 2 * tg;
            if (OUT == 0) {
                float* Cout = (float*)Cv;
                float2 f0 = { acc[mi][ni][0], acc[mi][ni][1] };
                float2 f1 = { acc[mi][ni][2], acc[mi][ni][3] };
                *(float2*)&Cout[(size_t)row0 * Nc + col] = f0;
                *(float2*)&Cout[(size_t)row1 * Nc + col] = f1;
            } else if (OUT == 1) {
                __half* Ch = (__half*)Cv;
                int h = col >> 5, rr = col & (R_ - 1);
                int b0r = row0 >> 11, n0r = row0 & (N_ - 1);
                int b1r = row1 >> 11, n1r = row1 & (N_ - 1);
                size_t i0 = ((((size_t)b0r * H_ + h) * N_) + n0r) * R_ + rr;
                size_t i1 = ((((size_t)b1r * H_ + h) * N_) + n1r) * R_ + rr;
                *(unsigned*)(Ch + i0) = packh2(acc[mi][ni][0] * oscale, acc[mi][ni][1] * oscale);
                *(unsigned*)(Ch + i1) = packh2(acc[mi][ni][2] * oscale, acc[mi][ni][3] * oscale);
            } else {  // OUT == 3: V transposed [B,H,R,N]
                __half* Ct = (__half*)Cv;
                int h = col >> 5, rr = col & (R_ - 1);
                int b0r = row0 >> 11, n0r = row0 & (N_ - 1);
                int b1r = row1 >> 11, n1r = row1 & (N_ - 1);
                Ct[(((size_t)b0r * H_ + h) * R_ + rr)     * N_ + n0r] = __float2half_rn(acc[mi][ni][0]);
                Ct[(((size_t)b0r * H_ + h) * R_ + rr + 1) * N_ + n0r] = __float2half_rn(acc[mi][ni][1]);
                Ct[(((size_t)b1r * H_ + h) * R_ + rr)     * N_ + n1r] = __float2half_rn(acc[mi][ni][2]);
                Ct[(((size_t)b1r * H_ + h) * R_ + rr + 1) * N_ + n1r] = __float2half_rn(acc[mi][ni][3]);
            }
        }
    }
}

__global__ __launch_bounds__(256) void qkv_proj_kernel(
    const __half* __restrict__ xh,
    const __half* __restrict__ wqt, const __half* __restrict__ wkt,
    const __half* __restrict__ wvt,
    __half* __restrict__ oq, __half* __restrict__ ok,
    __half* __restrict__ ovt)
{
    const int z = blockIdx.z;
    const int rb = blockIdx.y * 128, cb = blockIdx.x * 128;
    if (z == 0)      gemm_f16_body<1>(xh, wqt, oq, C_, HR_, rb, cb, QSCALE);
    else if (z == 1) gemm_f16_body<1>(xh, wkt, ok, C_, HR_, rb, cb, 1.0f);
    else             gemm_f16_body<3>(xh, wvt, ovt, C_, HR_, rb, cb, 1.0f);
}

__global__ __launch_bounds__(256) void out_proj_kernel(
    const __half* __restrict__ A, const __half* __restrict__ wpt,
    float* __restrict__ Cout)
{
    gemm_f16_body<0>(A, wpt, Cout, HR_, C_, blockIdx.y * 128, blockIdx.x * 128, 1.0f);
}

// ---------------------------------------------------------------------------
// Flash attention: full fp16 m16n8k16 (QK^T and P@V).
// Ks[key][r] half stride 20w. Vts[r][key] half stride 36w (V pre-transposed
// in gmem). Ps[qrow][key] half stride 36w. 128 thr, q-block 128.
// ---------------------------------------------------------------------------
#define KS_STRIDE 20
#define VT_STRIDE 36
#define PS_STRIDE 36
#define SMEM_ATTN ((64 * KS_STRIDE + 32 * VT_STRIDE + 128 * PS_STRIDE) * 4)

__global__ __launch_bounds__(128) void attn_tc_kernel(
    const __half* __restrict__ q, const __half* __restrict__ k,
    const __half* __restrict__ vt, __half* __restrict__ o)
{
    extern __shared__ unsigned smem[];
    unsigned (*Ks)[KS_STRIDE]  = (unsigned(*)[KS_STRIDE])smem;
    unsigned (*Vts)[VT_STRIDE] = (unsigned(*)[VT_STRIDE])(smem + 64 * KS_STRIDE);
    unsigned (*Ps)[PS_STRIDE]  = (unsigned(*)[PS_STRIDE])(smem + 64 * KS_STRIDE + 32 * VT_STRIDE);

    const int tid  = threadIdx.x;
    const int w    = tid >> 5;
    const int lane = tid & 31;
    const int g    = lane >> 2;
    const int tg   = lane & 3;
    const int bh   = blockIdx.y;
    const int qbase = blockIdx.x * 128;

    // Q fragments (half, pre-scaled)
    unsigned qa[2][2][4];
#pragma unroll
    for (int mi = 0; mi < 2; mi++) {
        const __half* q0 = q + ((size_t)bh * N_ + qbase + w * 32 + mi * 16 + g) * R_;
        const __half* q1 = q0 + 8 * R_;
#pragma unroll
        for (int c = 0; c < 2; c++) {
            qa[mi][c][0] = *(const unsigned*)(q0 + c * 16 + 2 * tg);
            qa[mi][c][1] = *(const unsigned*)(q1 + c * 16 + 2 * tg);
            qa[mi][c][2] = *(const unsigned*)(q0 + c * 16 + 2 * tg + 8);
            qa[mi][c][3] = *(const unsigned*)(q1 + c * 16 + 2 * tg + 8);
        }
    }

    float m[2][2] = { {-1e30f, -1e30f}, {-1e30f, -1e30f} };
    float l[2][2] = {};
    float oacc[2][4][4] = {};

    const uint4* kg = (const uint4*)(k  + (size_t)bh * N_ * R_);   // 8 halves each
    const uint4* vg = (const uint4*)(vt + (size_t)bh * R_ * N_);   // row r: 256 uint4

    // preload tile 0
#pragma unroll
    for (int j = 0; j < 2; j++) {           // K: 256 uint4/tile
        int idx = tid + j * 128;
        int key = idx >> 2, c4 = idx & 3;
        *(uint4*)&Ks[key][c4 * 4] = kg[idx];
    }
#pragma unroll
    for (int j = 0; j < 2; j++) {           // Vt: 32 rows x 8 uint4
        int idx = tid + j * 128;
        int r = idx >> 3, c = idx & 7;
        *(uint4*)&Vts[r][c * 4] = vg[r * 256 + c];
    }
    __syncthreads();

    const int NT = N_ / 64;
    for (int kt = 0; kt < NT; kt++) {
        uint4 kr[2], vr[2];
        if (kt + 1 < NT) {
            int kbase = (kt + 1) * 256;
#pragma unroll
            for (int j = 0; j < 2; j++) kr[j] = kg[kbase + tid + j * 128];
#pragma unroll
            for (int j = 0; j < 2; j++) {
                int idx = tid + j * 128;
                int r = idx >> 3, c = idx & 7;
                vr[j] = vg[r * 256 + (kt + 1) * 8 + c];
            }
        }

        // ---- S = Q @ K^T (fp16 k16) ----
        float s[2][8][4];
#pragma unroll
        for (int mi = 0; mi < 2; mi++)
#pragma unroll
            for (int nt = 0; nt < 8; nt++) {
                s[mi][nt][0] = 0; s[mi][nt][1] = 0; s[mi][nt][2] = 0; s[mi][nt][3] = 0;
            }
#pragma unroll
        for (int nt = 0; nt < 8; nt++) {
#pragma unroll
            for (int c = 0; c < 2; c++) {
                unsigned b0 = Ks[nt * 8 + g][c * 8 + tg];
                unsigned b1 = Ks[nt * 8 + g][c * 8 + tg + 4];
                mma_f16(s[0][nt], qa[0][c][0], qa[0][c][1], qa[0][c][2], qa[0][c][3], b0, b1);
                mma_f16(s[1][nt], qa[1][c][0], qa[1][c][1], qa[1][c][2], qa[1][c][3], b0, b1);
            }
        }

        // ---- online softmax + P store (half2) ----
#pragma unroll
        for (int mi = 0; mi < 2; mi++) {
            float r0 = -1e30f, r1 = -1e30f;
#pragma unroll
            for (int nt = 0; nt < 8; nt++) {
                r0 = fmaxf(r0, fmaxf(s[mi][nt][0], s[mi][nt][1]));
                r1 = fmaxf(r1, fmaxf(s[mi][nt][2], s[mi][nt][3]));
            }
            r0 = fmaxf(r0, __shfl_xor_sync(0xffffffff, r0, 1));
            r0 = fmaxf(r0, __shfl_xor_sync(0xffffffff, r0, 2));
            r1 = fmaxf(r1, __shfl_xor_sync(0xffffffff, r1, 1));
            r1 = fmaxf(r1, __shfl_xor_sync(0xffffffff, r1, 2));

            float mn0 = fmaxf(m[mi][0], r0), mn1 = fmaxf(m[mi][1], r1);
            float al0 = ex2(m[mi][0] - mn0), al1 = ex2(m[mi][1] - mn1);
            m[mi][0] = mn0; m[mi][1] = mn1;
            l[mi][0] *= al0; l[mi][1] *= al1;
#pragma unroll
            for (int nt = 0; nt < 4; nt++) {
                oacc[mi][nt][0] *= al0; oacc[mi][nt][1] *= al0;
                oacc[mi][nt][2] *= al1; oacc[mi][nt][3] *= al1;
            }

            const int prow0 = w * 32 + mi * 16 + g;
#pragma unroll
            for (int nt = 0; nt < 8; nt++) {
                float p0 = ex2(s[mi][nt][0] - mn0);
                float p1 = ex2(s[mi][nt][1] - mn0);
                float p2 = ex2(s[mi][nt][2] - mn1);
                float p3 = ex2(s[mi][nt][3] - mn1);
                l[mi][0] += p0 + p1;
                l[mi][1] += p2 + p3;
                Ps[prow0][nt * 4 + tg]     = packh2(p0, p1);
                Ps[prow0 + 8][nt * 4 + tg] = packh2(p2, p3);
            }
        }
        __syncwarp();

        // ---- O += P @ V (fp16 k16) ----
#pragma unroll
        for (int ks = 0; ks < 4; ks++) {
            unsigned b0[4], b1[4];
#pragma unroll
            for (int nt = 0; nt < 4; nt++) {
                int n = nt * 8 + g;
                b0[nt] = Vts[n][ks * 8 + tg];
                b1[nt] = Vts[n][ks * 8 + tg + 4];
            }
#pragma unroll
            for (int mi = 0; mi < 2; mi++) {
                const int prow = w * 32 + mi * 16 + g;
                unsigned a0 = Ps[prow][ks * 8 + tg];
                unsigned a1 = Ps[prow + 8][ks * 8 + tg];
                unsigned a2 = Ps[prow][ks * 8 + tg + 4];
                unsigned a3 = Ps[prow + 8][ks * 8 + tg + 4];
#pragma unroll
                for (int nt = 0; nt < 4; nt++)
                    mma_f16(oacc[mi][nt], a0, a1, a2, a3, b0[nt], b1[nt]);
            }
        }

        if (kt + 1 < NT) {
            __syncthreads();
#pragma unroll
            for (int j = 0; j < 2; j++) {
                int idx = tid + j * 128;
                int key = idx >> 2, c4 = idx & 3;
                *(uint4*)&Ks[key][c4 * 4] = kr[j];
            }
#pragma unroll
            for (int j = 0; j < 2; j++) {
                int idx = tid + j * 128;
                int r = idx >> 3, c = idx & 7;
                *(uint4*)&Vts[r][c * 4] = vr[j];
            }
            __syncthreads();
        }
    }

    // ---- finalize: normalize, store half ----
    const int b = bh / H_;
    const int h = bh % H_;
#pragma unroll
    for (int mi = 0; mi < 2; mi++) {
        float l0 = l[mi][0], l1 = l[mi][1];
        l0 += __shfl_xor_sync(0xffffffff, l0, 1);
        l0 += __shfl_xor_sync(0xffffffff, l0, 2);
        l1 += __shfl_xor_sync(0xffffffff, l1, 1);
        l1 += __shfl_xor_sync(0xffffffff, l1, 2);
        const float inv0 = 1.0f / l0;
        const float inv1 = 1.0f / l1;

        const int row0 = qbase + w * 32 + mi * 16 + g;
        const int row1 = row0 + 8;
        __half* o0 = o + (((size_t)b * N_ + row0) * H_ + h) * R_;
        __half* o1 = o + (((size_t)b * N_ + row1) * H_ + h) * R_;
#pragma unroll
        for (int nt = 0; nt < 4; nt++) {
            int col = nt * 8 + 2 * tg;
            *(unsigned*)(o0 + col) = packh2(oacc[mi][nt][0] * inv0, oacc[mi][nt][1] * inv0);
            *(unsigned*)(o1 + col) = packh2(oacc[mi][nt][2] * inv1, oacc[mi][nt][3] * inv1);
        }
    }
}

// ---------------------------------------------------------------------------
extern "C" void kernel_launch(void* const* d_in, const int* in_sizes, int n_in,
                              void* d_out, int out_size)
{
    const float* x  = (const float*)d_in[0];
    const float* Wq = (const float*)d_in[1];
    const float* Wk = (const float*)d_in[2];
    const float* Wv = (const float*)d_in[3];
    const float* Wp = (const float*)d_in[4];
    float* out = (float*)d_out;

    __half *xh, *wqt, *wkt, *wvt, *wpt, *qh, *kh, *vth, *oh;
    cudaGetSymbolAddress((void**)&xh,  g_xh);
    cudaGetSymbolAddress((void**)&wqt, g_wqt);
    cudaGetSymbolAddress((void**)&wkt, g_wkt);
    cudaGetSymbolAddress((void**)&wvt, g_wvt);
    cudaGetSymbolAddress((void**)&wpt, g_wpt);
    cudaGetSymbolAddress((void**)&qh,  g_qh);
    cudaGetSymbolAddress((void**)&kh,  g_kh);
    cudaGetSymbolAddress((void**)&vth, g_vt);
    cudaGetSymbolAddress((void**)&oh,  g_oh);

    static bool attr_set = false;
    if (!attr_set) {
        cudaFuncSetAttribute(attn_tc_kernel,
                             cudaFuncAttributeMaxDynamicSharedMemorySize, SMEM_ATTN);
        attr_set = true;
    }

    // prep: x->half, W transposes->half
    x_to_half_kernel<<<M_ * C_ / 2048, 256>>>(x, xh);
    dim3 gT(C_ / 32, C_ / 32, 4);
    w_transpose_kernel<<<gT, 256>>>(Wq, Wk, Wv, Wp, wqt, wkt, wvt, wpt);

    // QKV projections (fp16 tensor core; V written transposed)
    dim3 gProj(HR_ / 128, M_ / 128, 3);
    qkv_proj_kernel<<<gProj, 256>>>(xh, wqt, wkt, wvt, qh, kh, vth);

    // attention (all-fp16 tensor core)
    dim3 gAttn(N_ / 128, B_ * H_);
    attn_tc_kernel<<<gAttn, 128, SMEM_ATTN>>>(qh, kh, vth, oh);

    // output projection
    dim3 gOut(C_ / 128, M_ / 128);
    out_proj_kernel<<<gOut, 256>>>(oh, wpt, out);
}